// round 10
// baseline (speedup 1.0000x reference)
#include <cuda_runtime.h>
#include <cuda_bf16.h>
#include <cstdint>

// ---------------------------------------------------------------------------
// Problem constants
// ---------------------------------------------------------------------------
#define BATCH   32768
#define IMG     28
#define KPIX    784      // GEMM K
#define OUT_HW  26
#define OPIX    676
#define HID     200
#define HPAD    256      // padded hidden (GEMM N)
#define NOUT    10

#define BM      128      // M rows per CTA
#define BK      32       // K per chunk (bf16 -> 64B rows, SW64)
#define NCHUNK  25       // 24*32 + 16
#define NSTAGE  2        // ring depth (small smem -> 2 CTAs/SM)
#define GEMM_THREADS 256
#define NLOAD   224      // loader threads (warps 1..7)
#define NF4     (BM * (BK / 4))   // 1024 float4 per chunk
#define LPT     5                 // float4 per loader thread (224*5 >= 1024)

// idesc kind::f16 (bf16 in, fp32 acc), M=128, N=256
#define MMA_IDESC 0x8400490u

#if defined(__CUDA_ARCH__) && defined(__CUDA_ARCH_FEAT_SM103_ALL)
#define HAS_TCGEN05 1
#else
#define HAS_TCGEN05 0
#endif

// elements per B chunk block: [hi 256x32 | lo 256x32] = 16384 bf16 = 32KB
#define BCHUNK_ELEMS (2 * HPAD * BK)

// ---------------------------------------------------------------------------
// Global scratch.
//  g_B   : per chunk, 32KB contiguous [hi 16KB | lo 16KB], SW64 pre-swizzled
//  g_Weff: fp32 Weff for the portable fallback path (never runs on GB300)
// ---------------------------------------------------------------------------
__device__ __align__(16) __nv_bfloat16 g_B[NCHUNK * BCHUNK_ELEMS];
__device__ __align__(16) float         g_Weff[HPAD * KPIX];

// ---------------------------------------------------------------------------
// Arch-neutral helpers
// ---------------------------------------------------------------------------
__device__ __forceinline__ uint32_t smem_to_u32(const void* p) {
    uint32_t a;
    asm("{ .reg .u64 t; cvta.to.shared.u64 t, %1; cvt.u32.u64 %0, t; }"
        : "=r"(a) : "l"(p));
    return a;
}
__device__ __forceinline__ unsigned long long pack2(float lo, float hi) {
    unsigned long long r;
    asm("mov.b64 %0, {%1, %2};" : "=l"(r) : "f"(lo), "f"(hi));
    return r;
}
__device__ __forceinline__ void fma2(unsigned long long& d,
                                     unsigned long long a,
                                     unsigned long long b) {
    asm("fma.rn.f32x2 %0, %1, %2, %0;" : "+l"(d) : "l"(a), "l"(b));
}
__device__ __forceinline__ float2 unpack2(unsigned long long v) {
    float2 f;
    asm("mov.b64 {%0, %1}, %2;" : "=f"(f.x), "=f"(f.y) : "l"(v));
    return f;
}

#if HAS_TCGEN05
// ---------------------------------------------------------------------------
// tcgen05 / mbarrier / bulk-copy PTX helpers (sm_103a-only compilation)
// ---------------------------------------------------------------------------
__device__ __forceinline__ uint32_t elect_one_pred() {
    uint32_t pred;
    asm volatile(
        "{\n\t.reg .pred p;\n\t"
        "elect.sync _|p, 0xFFFFFFFF;\n\t"
        "selp.b32 %0, 1, 0, p;\n\t}"
        : "=r"(pred));
    return pred;
}

#define MBARRIER_INIT(addr, cnt) \
    asm volatile("mbarrier.init.shared.b64 [%0], %1;" \
        :: "r"((uint32_t)(addr)), "r"((uint32_t)(cnt)) : "memory")

#define MBARRIER_ARRIVE(addr) \
    asm volatile("mbarrier.arrive.release.cta.shared::cta.b64 _, [%0];" \
        :: "r"((uint32_t)(addr)) : "memory")

#define MBARRIER_EXPECT_TX(addr, bytes) \
    asm volatile("mbarrier.arrive.expect_tx.shared.b64 _, [%0], %1;" \
        :: "r"((uint32_t)(addr)), "r"((uint32_t)(bytes)) : "memory")

#define MBARRIER_WAIT_PARITY(addr, par) do { \
    uint32_t _m = (uint32_t)(addr); \
    uint32_t _p = (uint32_t)(par); \
    uint32_t _done; \
    asm volatile( \
        "{\n\t.reg .pred p;\n\t" \
        "mbarrier.try_wait.parity.acquire.cta.shared::cta.b64 p, [%1], %2;\n\t" \
        "selp.b32 %0, 1, 0, p;\n\t}" \
        : "=r"(_done) : "r"(_m), "r"(_p) : "memory"); \
    if (!_done) { \
        asm volatile( \
            "{\n\t.reg .pred P1;\n\t" \
            "WAIT_LOOP_%=:\n\t" \
            "mbarrier.try_wait.parity.acquire.cta.shared::cta.b64 P1, [%0], %1, 0x989680;\n\t" \
            "@P1 bra.uni WAIT_DONE_%=;\n\t" \
            "bra.uni WAIT_LOOP_%=;\n\t" \
            "WAIT_DONE_%=:\n\t}" \
            :: "r"(_m), "r"(_p) : "memory"); \
    } \
} while (0)

// plain bulk copy gmem -> smem, completion via tx mbarrier (UBLKCP)
#define CP_ASYNC_BULK_G2S(dst, src, bytes, mbar) \
    asm volatile( \
        "cp.async.bulk.shared::cluster.global.mbarrier::complete_tx::bytes " \
        "[%0], [%1], %2, [%3];" \
        :: "r"((uint32_t)(dst)), "l"(src), "r"((uint32_t)(bytes)), \
           "r"((uint32_t)(mbar)) : "memory")

#define TCGEN05_ALLOC(res_addr, ncols) \
    asm volatile("tcgen05.alloc.cta_group::1.sync.aligned.shared::cta.b32 [%0], %1;" \
        :: "r"((uint32_t)(res_addr)), "r"((uint32_t)(ncols)) : "memory")
#define TCGEN05_DEALLOC(tmem, ncols) \
    asm volatile("tcgen05.dealloc.cta_group::1.sync.aligned.b32 %0, %1;" \
        :: "r"(tmem), "r"((uint32_t)(ncols)))
#define TCGEN05_RELINQUISH() \
    asm volatile("tcgen05.relinquish_alloc_permit.cta_group::1.sync.aligned;")
#define TCGEN05_COMMIT(mbar) \
    asm volatile("tcgen05.commit.cta_group::1.mbarrier::arrive::one.shared::cluster.b64 [%0];" \
        :: "r"((uint32_t)(mbar)) : "memory")
#define TCGEN05_WAIT_LD() \
    asm volatile("tcgen05.wait::ld.sync.aligned;" ::: "memory")
#define TCGEN05_FENCE_BEFORE() \
    asm volatile("tcgen05.fence::before_thread_sync;" ::: "memory")
#define TCGEN05_FENCE_AFTER() \
    asm volatile("tcgen05.fence::after_thread_sync;" ::: "memory")
#define FENCE_PROXY_ASYNC() \
    asm volatile("fence.proxy.async.shared::cta;" ::: "memory")

#define TCGEN05_LD_32X32B_X32(r, tmem_addr) \
    asm volatile( \
        "tcgen05.ld.sync.aligned.32x32b.x32.b32 " \
        "{%0, %1, %2, %3, %4, %5, %6, %7, " \
        " %8, %9, %10, %11, %12, %13, %14, %15, " \
        " %16, %17, %18, %19, %20, %21, %22, %23, " \
        " %24, %25, %26, %27, %28, %29, %30, %31}, [%32];" \
        : "=r"((r)[0]),  "=r"((r)[1]),  "=r"((r)[2]),  "=r"((r)[3]), \
          "=r"((r)[4]),  "=r"((r)[5]),  "=r"((r)[6]),  "=r"((r)[7]), \
          "=r"((r)[8]),  "=r"((r)[9]),  "=r"((r)[10]), "=r"((r)[11]), \
          "=r"((r)[12]), "=r"((r)[13]), "=r"((r)[14]), "=r"((r)[15]), \
          "=r"((r)[16]), "=r"((r)[17]), "=r"((r)[18]), "=r"((r)[19]), \
          "=r"((r)[20]), "=r"((r)[21]), "=r"((r)[22]), "=r"((r)[23]), \
          "=r"((r)[24]), "=r"((r)[25]), "=r"((r)[26]), "=r"((r)[27]), \
          "=r"((r)[28]), "=r"((r)[29]), "=r"((r)[30]), "=r"((r)[31]) \
        : "r"(tmem_addr))

// SW64 K-major descriptor (layout=4, version=1, SBO=32 (512B = 8 rows x 64B),
// LBO=1 (16B)) — 64-byte rows.
static constexpr uint64_t SMEM_DESC_BASE_SW64 =
    (uint64_t(4)  << 61) | (uint64_t(1) << 46) |
    (uint64_t(32) << 32) | (uint64_t(1) << 16);
#define MAKE_SMEM_DESC64(addr) \
    (SMEM_DESC_BASE_SW64 | ((uint64_t)((addr) >> 4) & 0x3FFF))

__device__ __forceinline__ void mma_f16_ss(uint32_t d_tmem, uint64_t a_desc,
                                           uint64_t b_desc, uint32_t idesc,
                                           bool acc) {
    uint32_t en = acc ? 1u : 0u;
    asm volatile(
        "{\n\t.reg .pred p;\n\t"
        "setp.ne.u32 p, %5, 0;\n\t"
        "tcgen05.mma.cta_group::1.kind::f16 [%0], %1, %2, %3, "
        "{%4, %4, %4, %4}, p;\n\t}"
        :: "r"(d_tmem), "l"(a_desc), "l"(b_desc), "r"(idesc),
           "r"(0u), "r"(en)
        : "memory");
}
#endif // HAS_TCGEN05

// SW64 swizzle (bits [5:4] ^= bits [8:7])
__host__ __device__ __forceinline__ uint32_t sw64(uint32_t off) {
    return off ^ ((off >> 3) & 0x30);
}

// ---------------------------------------------------------------------------
// Kernel 1: fold conv into w0; write fp32 g_Weff (fallback) and SW64
// pre-swizzled bf16 hi/lo chunk blocks g_B. grid=HPAD, block=800 (25*32).
// ---------------------------------------------------------------------------
__global__ void build_weff_kernel(const float* __restrict__ conv_w,
                                  const float* __restrict__ w0) {
    int j = blockIdx.x;      // hidden unit 0..255
    int p = threadIdx.x;     // k position 0..799
    float s = 0.0f;
    if (j < HID && p < KPIX) {
        int py = p / IMG, px = p % IMG;
        #pragma unroll
        for (int ky = 0; ky < 3; ky++)
            #pragma unroll
            for (int kx = 0; kx < 3; kx++) {
                int oy = py - ky, ox = px - kx;
                if (oy >= 0 && oy < OUT_HW && ox >= 0 && ox < OUT_HW)
                    s += conv_w[ky * 3 + kx] * w0[j * OPIX + oy * OUT_HW + ox];
            }
    }
    if (p < KPIX) g_Weff[j * KPIX + p] = s;

    __nv_bfloat16 hi = __float2bfloat16_rn(s);
    __nv_bfloat16 lo = __float2bfloat16_rn(s - __bfloat162float(hi));
    int chunk = p >> 5, kin = p & 31;                // BK=32
    uint32_t off = (uint32_t)(j * 64 + kin * 2);     // bytes within 16KB tile
    uint32_t sw  = sw64(off);
    int base = chunk * BCHUNK_ELEMS;                 // [hi 8192 | lo 8192]
    g_B[base + (int)(sw >> 1)]                 = hi;
    g_B[base + HPAD * BK + (int)(sw >> 1)]     = lo;
}

// ---------------------------------------------------------------------------
// Kernel 2: fused  out = relu(X @ WeffT + b0) @ w1T + b1  (tcgen05, 2-way
// bf16 split). Warp-specialized, 2-stage ring, 108KB smem -> TWO CTAs PER SM:
// one CTA's sync bubbles are filled by the other CTA's MMA/loads, and the
// grid (256 CTAs) becomes a single wave.
// ---------------------------------------------------------------------------
// smem byte offsets
// ctrl: tmem ptr @0; bfull[2] @16,24; afull[2] @32,40; mdone[2] @48,56;
//       alldone @64
#define SM_CTRL   0
#define SM_A      1024       // 2 stages x (hi 8KB | lo 8KB) = 32768
#define SM_B      33792      // 2 stages x (hi 16KB | lo 16KB) = 65536
#define SM_W1P    99328      // 256*5*8 = 10240
#define SM_B0     109568     // 1024
#define SM_OUT    SM_A       // reused AFTER mainloop (A ring is dead)
#define SMEM_TOTAL 110592    // 108KB -> 2 CTAs/SM

__global__ void __launch_bounds__(GEMM_THREADS, 2)
gemm_fused_kernel(const float* __restrict__ X,
                  const float* __restrict__ b0,
                  const float* __restrict__ w1,
                  const float* __restrict__ b1,
                  float* __restrict__ out) {
#if HAS_TCGEN05
    extern __shared__ char smem[];
    const uint32_t smem_base = smem_to_u32(smem);
    const int tid = threadIdx.x;
    const int wid = tid >> 5;
    const int lid = tid & 31;
    const int m0  = blockIdx.x * BM;

    const uint32_t mb_bfull   = smem_base + SM_CTRL + 16;  // +8*s
    const uint32_t mb_afull   = smem_base + SM_CTRL + 32;  // +8*s
    const uint32_t mb_mdone   = smem_base + SM_CTRL + 48;  // +8*s
    const uint32_t mb_alldone = smem_base + SM_CTRL + 64;

    // TMEM alloc (warp 0, collective): 256 fp32 accumulator columns.
    // Two co-resident CTAs each take 256 of the SM's 512 columns.
    if (wid == 0) TCGEN05_ALLOC(smem_base + SM_CTRL, 256);

    // epilogue weights into smem + mbarrier init
    if (tid < HPAD) {
        int j = tid;
        float* b0s = (float*)(smem + SM_B0);
        b0s[j] = (j < HID) ? b0[j] : 0.0f;
        unsigned long long* w1p = (unsigned long long*)(smem + SM_W1P);
        #pragma unroll
        for (int cc = 0; cc < 5; cc++) {
            float a  = (j < HID) ? w1[(2 * cc) * HID + j] : 0.0f;
            float bb = (j < HID) ? w1[(2 * cc + 1) * HID + j] : 0.0f;
            w1p[j * 5 + cc] = pack2(a, bb);
        }
    }
    if (tid == 0) {
        #pragma unroll
        for (int s = 0; s < NSTAGE; s++) {
            MBARRIER_INIT(mb_bfull + 8 * s, 1);
            MBARRIER_INIT(mb_afull + 8 * s, 1);
            MBARRIER_INIT(mb_mdone + 8 * s, 1);
        }
        MBARRIER_INIT(mb_alldone, 1);
    }
    __syncthreads();

    uint32_t tmem;
    asm volatile("ld.shared.b32 %0, [%1];" : "=r"(tmem) : "r"(smem_base + SM_CTRL));

    if (wid == 0) {
        // =================== MMA issuer (warp 0) ===================
        for (int c = 0; c < NCHUNK; c++) {
            const int s  = c & 1;
            const int ph = (c >> 1) & 1;          // producer arrival parity
            MBARRIER_WAIT_PARITY(mb_afull + 8 * s, ph);
            MBARRIER_WAIT_PARITY(mb_bfull + 8 * s, ph);
            if (elect_one_pred()) {
                TCGEN05_FENCE_AFTER();
                uint64_t ah = MAKE_SMEM_DESC64(smem_base + SM_A + s * 16384);
                uint64_t al = MAKE_SMEM_DESC64(smem_base + SM_A + s * 16384 + 8192);
                uint64_t bh = MAKE_SMEM_DESC64(smem_base + SM_B + s * 32768);
                uint64_t bl = MAKE_SMEM_DESC64(smem_base + SM_B + s * 32768 + 16384);
                int nst = (c == NCHUNK - 1) ? 1 : 2;   // K=16 per MMA step
                for (int ks = 0; ks < nst; ks++) {
                    uint64_t o = (uint64_t)(ks * 2);   // +32B per 16 bf16
                    mma_f16_ss(tmem, ah + o, bh + o, MMA_IDESC, !(c == 0 && ks == 0));
                    mma_f16_ss(tmem, ah + o, bl + o, MMA_IDESC, true);
                    mma_f16_ss(tmem, al + o, bh + o, MMA_IDESC, true);
                }
                TCGEN05_COMMIT(mb_mdone + 8 * s);
                if (c == NCHUNK - 1) TCGEN05_COMMIT(mb_alldone);
            }
        }
    } else {
        // ==================== loaders (warps 1-7) ====================
        const int ltid = tid - 32;   // 0..223

        // Phase 1: batch global loads for chunk c into registers (zero-filled).
        auto load_regs = [&](int c, float4* v) {
            const int kvalid = KPIX - c * BK;   // 32 except last chunk = 16
            #pragma unroll
            for (int i = 0; i < LPT; i++) {
                v[i] = make_float4(0.f, 0.f, 0.f, 0.f);
                int idx  = ltid + i * NLOAD;
                int row  = idx >> 3;       // 0..127
                int col4 = idx & 7;        // float4 within 32-col chunk
                if (idx < NF4 && col4 * 4 < kvalid) {
                    v[i] = *(const float4*)(
                        X + (long)(m0 + row) * KPIX + c * BK + col4 * 4);
                }
            }
        };
        // Phase 2: convert bf16 hi/lo + SW64 STS (always store; zeros pad).
        auto store_stage = [&](int s, const float4* v) {
            char* ahi = smem + SM_A + s * 16384;
            char* alo = ahi + 8192;
            #pragma unroll
            for (int i = 0; i < LPT; i++) {
                int idx  = ltid + i * NLOAD;
                int row  = idx >> 3;
                int col4 = idx & 7;
                if (idx < NF4) {
                    __nv_bfloat16 h0 = __float2bfloat16_rn(v[i].x);
                    __nv_bfloat16 h1 = __float2bfloat16_rn(v[i].y);
                    __nv_bfloat16 h2 = __float2bfloat16_rn(v[i].z);
                    __nv_bfloat16 h3 = __float2bfloat16_rn(v[i].w);
                    __nv_bfloat16 l0 = __float2bfloat16_rn(v[i].x - __bfloat162float(h0));
                    __nv_bfloat16 l1 = __float2bfloat16_rn(v[i].y - __bfloat162float(h1));
                    __nv_bfloat16 l2 = __float2bfloat16_rn(v[i].z - __bfloat162float(h2));
                    __nv_bfloat16 l3 = __float2bfloat16_rn(v[i].w - __bfloat162float(h3));
                    __nv_bfloat162 hp0{h0, h1}, hp1{h2, h3};
                    __nv_bfloat162 lp0{l0, l1}, lp1{l2, l3};
                    uint2 hv, lv;
                    hv.x = *(uint32_t*)&hp0; hv.y = *(uint32_t*)&hp1;
                    lv.x = *(uint32_t*)&lp0; lv.y = *(uint32_t*)&lp1;
                    uint32_t sw = sw64((uint32_t)(row * 64 + col4 * 8));
                    *(uint2*)(ahi + sw) = hv;
                    *(uint2*)(alo + sw) = lv;
                }
            }
        };
        // All loader warps synced, then one thread arrives (afull count=1).
        auto publish = [&](int s) {
            FENCE_PROXY_ASYNC();
            asm volatile("bar.sync 1, %0;" :: "r"(NLOAD) : "memory");
            if (tid == 32) MBARRIER_ARRIVE(mb_afull + 8 * s);
        };
        auto b_copy = [&](int c, int s) {
            MBARRIER_EXPECT_TX(mb_bfull + 8 * s, 32768);
            CP_ASYNC_BULK_G2S(smem_base + SM_B + s * 32768,
                              (const void*)(g_B + c * BCHUNK_ELEMS),
                              32768, mb_bfull + 8 * s);
        };

        // prologue: fill both stages (chunks 0, 1)
        if (tid == 32) { b_copy(0, 0); b_copy(1, 1); }
        {
            float4 va[LPT], vb[LPT];
            load_regs(0, va); load_regs(1, vb);
            store_stage(0, va); publish(0);
            store_stage(1, vb); publish(1);
        }

        // main loop: chunk c reuses stage c&1 after MMA(c-2) completes.
        for (int c = NSTAGE; c < NCHUNK; c++) {
            const int s  = c & 1;
            const int ph = ((c >> 1) - 1) & 1;   // parity of commit from c-2
            float4 v[LPT];
            load_regs(c, v);                     // overlaps the mdone wait
            MBARRIER_WAIT_PARITY(mb_mdone + 8 * s, ph);
            if (tid == 32) b_copy(c, s);
            store_stage(s, v);
            publish(s);
        }
    }

    // ---- all threads: wait for every MMA to complete ----
    MBARRIER_WAIT_PARITY(mb_alldone, 0);
    __syncthreads();
    TCGEN05_FENCE_AFTER();

    // ---- fused epilogue: h = relu(D + b0); out = h @ w1T + b1 ----
    const int sub  = wid & 3;          // TMEM subpartition (rows sub*32..+31)
    const int half = wid >> 2;         // 0: cols 0..127, 1: cols 128..255
    const int r    = sub * 32 + lid;
    const float* b0s = (const float*)(smem + SM_B0);
    const unsigned long long* w1p = (const unsigned long long*)(smem + SM_W1P);

    unsigned long long p2[5] = {0, 0, 0, 0, 0};
    #pragma unroll
    for (int blk = 0; blk < 4; blk++) {
        uint32_t d[32];
        TCGEN05_LD_32X32B_X32(d, tmem + half * 128 + blk * 32);
        TCGEN05_WAIT_LD();
        #pragma unroll
        for (int i = 0; i < 32; i++) {
            int j = half * 128 + blk * 32 + i;
            float h = fmaxf(__uint_as_float(d[i]) + b0s[j], 0.0f);
            unsigned long long hh = pack2(h, h);
            #pragma unroll
            for (int cc = 0; cc < 5; cc++) fma2(p2[cc], hh, w1p[j * 5 + cc]);
        }
    }
    TCGEN05_FENCE_BEFORE();

    // A ring is dead after the mainloop; reuse it as the output staging buf.
    float* outst = (float*)(smem + SM_OUT);
    if (half == 0) {
        #pragma unroll
        for (int cc = 0; cc < 5; cc++) {
            float2 f = unpack2(p2[cc]);
            outst[r * 10 + 2 * cc]     = f.x;
            outst[r * 10 + 2 * cc + 1] = f.y;
        }
    }
    __syncthreads();
    if (half == 1) {
        long m = m0 + r;
        #pragma unroll
        for (int cc = 0; cc < 5; cc++) {
            float2 f = unpack2(p2[cc]);
            out[m * NOUT + 2 * cc]     = outst[r * 10 + 2 * cc]     + f.x + b1[2 * cc];
            out[m * NOUT + 2 * cc + 1] = outst[r * 10 + 2 * cc + 1] + f.y + b1[2 * cc + 1];
        }
    }
    __syncthreads();

    if (wid == 0) {
        TCGEN05_RELINQUISH();
        TCGEN05_DEALLOC(tmem, 256);
    }

#else  // ---------------- portable fallback (non-sm_103a passes) ------------
    extern __shared__ char smem[];
    const int tid  = threadIdx.x;
    const int r    = tid & 127;
    const int half = tid >> 7;
    const int m0   = blockIdx.x * BM;
    float* hbuf = (float*)smem;   // fits: 110592 > 128*200*4 requires 100KB ✓

    const float* xr = X + (long)(m0 + r) * KPIX;
    for (int j = half * 100; j < half * 100 + 100; j++) {
        const float* wr = g_Weff + j * KPIX;
        float s = 0.0f;
        for (int k = 0; k < KPIX; k += 4) {
            float4 xv = *(const float4*)(xr + k);
            float4 wv = *(const float4*)(wr + k);
            s += xv.x * wv.x + xv.y * wv.y + xv.z * wv.z + xv.w * wv.w;
        }
        hbuf[r * HID + j] = fmaxf(s + b0[j], 0.0f);
    }
    __syncthreads();
    if (half == 0) {
        float o[NOUT];
        #pragma unroll
        for (int c = 0; c < NOUT; c++) o[c] = b1[c];
        for (int j = 0; j < HID; j++) {
            float h = hbuf[r * HID + j];
            #pragma unroll
            for (int c = 0; c < NOUT; c++) o[c] += h * w1[c * HID + j];
        }
        #pragma unroll
        for (int c = 0; c < NOUT; c++) out[(long)(m0 + r) * NOUT + c] = o[c];
    }
#endif
}

// ---------------------------------------------------------------------------
// kernel_launch: graph-capturable, allocation-free.
// Inputs (metadata order): x, conv_w, w0, b0, w1, b1
// ---------------------------------------------------------------------------
extern "C" void kernel_launch(void* const* d_in, const int* in_sizes, int n_in,
                              void* d_out, int out_size) {
    const float* x      = (const float*)d_in[0];
    const float* conv_w = (const float*)d_in[1];
    const float* w0     = (const float*)d_in[2];
    const float* b0     = (const float*)d_in[3];
    const float* w1     = (const float*)d_in[4];
    const float* b1     = (const float*)d_in[5];
    float* out = (float*)d_out;

    cudaFuncSetAttribute(gemm_fused_kernel,
                         cudaFuncAttributeMaxDynamicSharedMemorySize, SMEM_TOTAL);

    build_weff_kernel<<<HPAD, NCHUNK * BK>>>(conv_w, w0);
    gemm_fused_kernel<<<BATCH / BM, GEMM_THREADS, SMEM_TOTAL>>>(x, b0, w1, b1, out);
}

// round 11
// speedup vs baseline: 1.0923x; 1.0923x over previous
#include <cuda_runtime.h>
#include <cuda_bf16.h>
#include <cstdint>

// ---------------------------------------------------------------------------
// Problem constants
// ---------------------------------------------------------------------------
#define BATCH   32768
#define IMG     28
#define KPIX    784      // GEMM K
#define OUT_HW  26
#define OPIX    676
#define HID     200
#define HPAD    256      // padded hidden (GEMM N)
#define NOUT    10

#define BM      256      // M rows per CTA = 2 tiles of 128 (dual TMEM accum)
#define BK      32       // K per chunk (bf16 -> 64B rows, SW64)
#define NCHUNK  25       // 24*32 + 16
#define NSTAGE  3        // ring depth
#define GEMM_THREADS 256
#define NLOAD   224      // loader threads (warps 1..7)
#define NF4     (BM * (BK / 4))   // 2048 float4 per chunk (256 rows x 8)
#define LPT     10                // float4 per loader thread (224*10 >= 2048)

// idesc kind::f16 (bf16 in, fp32 acc), M=128 (per tile), N=256
#define MMA_IDESC 0x8400490u

#if defined(__CUDA_ARCH__) && defined(__CUDA_ARCH_FEAT_SM103_ALL)
#define HAS_TCGEN05 1
#else
#define HAS_TCGEN05 0
#endif

// elements per B chunk block: [hi 256x32 | lo 256x32] = 16384 bf16 = 32KB
#define BCHUNK_ELEMS (2 * HPAD * BK)

// ---------------------------------------------------------------------------
// Global scratch.
//  g_B   : per chunk, 32KB contiguous [hi 16KB | lo 16KB], SW64 pre-swizzled
//  g_Weff: fp32 Weff for the portable fallback path (never runs on GB300)
// ---------------------------------------------------------------------------
__device__ __align__(16) __nv_bfloat16 g_B[NCHUNK * BCHUNK_ELEMS];
__device__ __align__(16) float         g_Weff[HPAD * KPIX];

// ---------------------------------------------------------------------------
// Arch-neutral helpers
// ---------------------------------------------------------------------------
__device__ __forceinline__ uint32_t smem_to_u32(const void* p) {
    uint32_t a;
    asm("{ .reg .u64 t; cvta.to.shared.u64 t, %1; cvt.u32.u64 %0, t; }"
        : "=r"(a) : "l"(p));
    return a;
}
__device__ __forceinline__ unsigned long long pack2(float lo, float hi) {
    unsigned long long r;
    asm("mov.b64 %0, {%1, %2};" : "=l"(r) : "f"(lo), "f"(hi));
    return r;
}
__device__ __forceinline__ void fma2(unsigned long long& d,
                                     unsigned long long a,
                                     unsigned long long b) {
    asm("fma.rn.f32x2 %0, %1, %2, %0;" : "+l"(d) : "l"(a), "l"(b));
}
__device__ __forceinline__ float2 unpack2(unsigned long long v) {
    float2 f;
    asm("mov.b64 {%0, %1}, %2;" : "=f"(f.x), "=f"(f.y) : "l"(v));
    return f;
}

#if HAS_TCGEN05
// ---------------------------------------------------------------------------
// tcgen05 / mbarrier / bulk-copy PTX helpers (sm_103a-only compilation)
// ---------------------------------------------------------------------------
__device__ __forceinline__ uint32_t elect_one_pred() {
    uint32_t pred;
    asm volatile(
        "{\n\t.reg .pred p;\n\t"
        "elect.sync _|p, 0xFFFFFFFF;\n\t"
        "selp.b32 %0, 1, 0, p;\n\t}"
        : "=r"(pred));
    return pred;
}

#define MBARRIER_INIT(addr, cnt) \
    asm volatile("mbarrier.init.shared.b64 [%0], %1;" \
        :: "r"((uint32_t)(addr)), "r"((uint32_t)(cnt)) : "memory")

#define MBARRIER_ARRIVE(addr) \
    asm volatile("mbarrier.arrive.release.cta.shared::cta.b64 _, [%0];" \
        :: "r"((uint32_t)(addr)) : "memory")

#define MBARRIER_EXPECT_TX(addr, bytes) \
    asm volatile("mbarrier.arrive.expect_tx.shared.b64 _, [%0], %1;" \
        :: "r"((uint32_t)(addr)), "r"((uint32_t)(bytes)) : "memory")

#define MBARRIER_WAIT_PARITY(addr, par) do { \
    uint32_t _m = (uint32_t)(addr); \
    uint32_t _p = (uint32_t)(par); \
    uint32_t _done; \
    asm volatile( \
        "{\n\t.reg .pred p;\n\t" \
        "mbarrier.try_wait.parity.acquire.cta.shared::cta.b64 p, [%1], %2;\n\t" \
        "selp.b32 %0, 1, 0, p;\n\t}" \
        : "=r"(_done) : "r"(_m), "r"(_p) : "memory"); \
    if (!_done) { \
        asm volatile( \
            "{\n\t.reg .pred P1;\n\t" \
            "WAIT_LOOP_%=:\n\t" \
            "mbarrier.try_wait.parity.acquire.cta.shared::cta.b64 P1, [%0], %1, 0x989680;\n\t" \
            "@P1 bra.uni WAIT_DONE_%=;\n\t" \
            "bra.uni WAIT_LOOP_%=;\n\t" \
            "WAIT_DONE_%=:\n\t}" \
            :: "r"(_m), "r"(_p) : "memory"); \
    } \
} while (0)

// plain bulk copy gmem -> smem, completion via tx mbarrier (UBLKCP)
#define CP_ASYNC_BULK_G2S(dst, src, bytes, mbar) \
    asm volatile( \
        "cp.async.bulk.shared::cluster.global.mbarrier::complete_tx::bytes " \
        "[%0], [%1], %2, [%3];" \
        :: "r"((uint32_t)(dst)), "l"(src), "r"((uint32_t)(bytes)), \
           "r"((uint32_t)(mbar)) : "memory")

#define TCGEN05_ALLOC(res_addr, ncols) \
    asm volatile("tcgen05.alloc.cta_group::1.sync.aligned.shared::cta.b32 [%0], %1;" \
        :: "r"((uint32_t)(res_addr)), "r"((uint32_t)(ncols)) : "memory")
#define TCGEN05_DEALLOC(tmem, ncols) \
    asm volatile("tcgen05.dealloc.cta_group::1.sync.aligned.b32 %0, %1;" \
        :: "r"(tmem), "r"((uint32_t)(ncols)))
#define TCGEN05_RELINQUISH() \
    asm volatile("tcgen05.relinquish_alloc_permit.cta_group::1.sync.aligned;")
#define TCGEN05_COMMIT(mbar) \
    asm volatile("tcgen05.commit.cta_group::1.mbarrier::arrive::one.shared::cluster.b64 [%0];" \
        :: "r"((uint32_t)(mbar)) : "memory")
#define TCGEN05_WAIT_LD() \
    asm volatile("tcgen05.wait::ld.sync.aligned;" ::: "memory")
#define TCGEN05_FENCE_BEFORE() \
    asm volatile("tcgen05.fence::before_thread_sync;" ::: "memory")
#define TCGEN05_FENCE_AFTER() \
    asm volatile("tcgen05.fence::after_thread_sync;" ::: "memory")
#define FENCE_PROXY_ASYNC() \
    asm volatile("fence.proxy.async.shared::cta;" ::: "memory")

#define TCGEN05_LD_32X32B_X32(r, tmem_addr) \
    asm volatile( \
        "tcgen05.ld.sync.aligned.32x32b.x32.b32 " \
        "{%0, %1, %2, %3, %4, %5, %6, %7, " \
        " %8, %9, %10, %11, %12, %13, %14, %15, " \
        " %16, %17, %18, %19, %20, %21, %22, %23, " \
        " %24, %25, %26, %27, %28, %29, %30, %31}, [%32];" \
        : "=r"((r)[0]),  "=r"((r)[1]),  "=r"((r)[2]),  "=r"((r)[3]), \
          "=r"((r)[4]),  "=r"((r)[5]),  "=r"((r)[6]),  "=r"((r)[7]), \
          "=r"((r)[8]),  "=r"((r)[9]),  "=r"((r)[10]), "=r"((r)[11]), \
          "=r"((r)[12]), "=r"((r)[13]), "=r"((r)[14]), "=r"((r)[15]), \
          "=r"((r)[16]), "=r"((r)[17]), "=r"((r)[18]), "=r"((r)[19]), \
          "=r"((r)[20]), "=r"((r)[21]), "=r"((r)[22]), "=r"((r)[23]), \
          "=r"((r)[24]), "=r"((r)[25]), "=r"((r)[26]), "=r"((r)[27]), \
          "=r"((r)[28]), "=r"((r)[29]), "=r"((r)[30]), "=r"((r)[31]) \
        : "r"(tmem_addr))

// SW64 K-major descriptor (layout=4, version=1, SBO=32 (512B = 8 rows x 64B),
// LBO=1 (16B)) — 64-byte rows.
static constexpr uint64_t SMEM_DESC_BASE_SW64 =
    (uint64_t(4)  << 61) | (uint64_t(1) << 46) |
    (uint64_t(32) << 32) | (uint64_t(1) << 16);
#define MAKE_SMEM_DESC64(addr) \
    (SMEM_DESC_BASE_SW64 | ((uint64_t)((addr) >> 4) & 0x3FFF))

__device__ __forceinline__ void mma_f16_ss(uint32_t d_tmem, uint64_t a_desc,
                                           uint64_t b_desc, uint32_t idesc,
                                           bool acc) {
    uint32_t en = acc ? 1u : 0u;
    asm volatile(
        "{\n\t.reg .pred p;\n\t"
        "setp.ne.u32 p, %5, 0;\n\t"
        "tcgen05.mma.cta_group::1.kind::f16 [%0], %1, %2, %3, "
        "{%4, %4, %4, %4}, p;\n\t}"
        :: "r"(d_tmem), "l"(a_desc), "l"(b_desc), "r"(idesc),
           "r"(0u), "r"(en)
        : "memory");
}
#endif // HAS_TCGEN05

// SW64 swizzle (bits [5:4] ^= bits [8:7])
__host__ __device__ __forceinline__ uint32_t sw64(uint32_t off) {
    return off ^ ((off >> 3) & 0x30);
}

// ---------------------------------------------------------------------------
// Kernel 1: fold conv into w0; write fp32 g_Weff (fallback) and SW64
// pre-swizzled bf16 hi/lo chunk blocks g_B. grid=HPAD, block=800 (25*32).
// ---------------------------------------------------------------------------
__global__ void build_weff_kernel(const float* __restrict__ conv_w,
                                  const float* __restrict__ w0) {
    int j = blockIdx.x;      // hidden unit 0..255
    int p = threadIdx.x;     // k position 0..799
    float s = 0.0f;
    if (j < HID && p < KPIX) {
        int py = p / IMG, px = p % IMG;
        #pragma unroll
        for (int ky = 0; ky < 3; ky++)
            #pragma unroll
            for (int kx = 0; kx < 3; kx++) {
                int oy = py - ky, ox = px - kx;
                if (oy >= 0 && oy < OUT_HW && ox >= 0 && ox < OUT_HW)
                    s += conv_w[ky * 3 + kx] * w0[j * OPIX + oy * OUT_HW + ox];
            }
    }
    if (p < KPIX) g_Weff[j * KPIX + p] = s;

    __nv_bfloat16 hi = __float2bfloat16_rn(s);
    __nv_bfloat16 lo = __float2bfloat16_rn(s - __bfloat162float(hi));
    int chunk = p >> 5, kin = p & 31;                // BK=32
    uint32_t off = (uint32_t)(j * 64 + kin * 2);     // bytes within 16KB tile
    uint32_t sw  = sw64(off);
    int base = chunk * BCHUNK_ELEMS;                 // [hi 8192 | lo 8192]
    g_B[base + (int)(sw >> 1)]                 = hi;
    g_B[base + HPAD * BK + (int)(sw >> 1)]     = lo;
}

// ---------------------------------------------------------------------------
// Kernel 2: fused  out = relu(X @ WeffT + b0) @ w1T + b1  (tcgen05, 2-way
// bf16 split). BM=256 per CTA as TWO M=128 tiles sharing each B chunk,
// dual TMEM accumulators (cols 0-255 / 256-511). 128 CTAs = single wave;
// MMA per chunk doubled (1536 cyc) so the handshake chain is amortized.
// ---------------------------------------------------------------------------
// smem byte offsets
// ctrl: tmem ptr @0; bfull[3] @16..39; afull[3] @48..71; mdone[3] @80..103;
//       alldone @112
#define SM_CTRL   0
#define SM_A      1024       // 3 stages x 32KB (t0hi|t0lo|t1hi|t1lo) = 98304
#define SM_B      99328      // 3 stages x 32KB (hi 16KB | lo 16KB)   = 98304
#define SM_W1P    197632     // 256*5*8 = 10240
#define SM_B0     207872     // 1024
#define SM_OUT    SM_A       // reused AFTER mainloop (A ring dead): 256*10*4
#define SMEM_TOTAL 208896    // 204KB

__global__ void __launch_bounds__(GEMM_THREADS, 1)
gemm_fused_kernel(const float* __restrict__ X,
                  const float* __restrict__ b0,
                  const float* __restrict__ w1,
                  const float* __restrict__ b1,
                  float* __restrict__ out) {
#if HAS_TCGEN05
    extern __shared__ char smem[];
    const uint32_t smem_base = smem_to_u32(smem);
    const int tid = threadIdx.x;
    const int wid = tid >> 5;
    const int lid = tid & 31;
    const int m0  = blockIdx.x * BM;

    const uint32_t mb_bfull   = smem_base + SM_CTRL + 16;  // +8*s
    const uint32_t mb_afull   = smem_base + SM_CTRL + 48;  // +8*s
    const uint32_t mb_mdone   = smem_base + SM_CTRL + 80;  // +8*s
    const uint32_t mb_alldone = smem_base + SM_CTRL + 112;

    // TMEM alloc (warp 0, collective): all 512 columns (two 256-col tiles)
    if (wid == 0) TCGEN05_ALLOC(smem_base + SM_CTRL, 512);

    // epilogue weights into smem + mbarrier init
    if (tid < HPAD) {
        int j = tid;
        float* b0s = (float*)(smem + SM_B0);
        b0s[j] = (j < HID) ? b0[j] : 0.0f;
        unsigned long long* w1p = (unsigned long long*)(smem + SM_W1P);
        #pragma unroll
        for (int cc = 0; cc < 5; cc++) {
            float a  = (j < HID) ? w1[(2 * cc) * HID + j] : 0.0f;
            float bb = (j < HID) ? w1[(2 * cc + 1) * HID + j] : 0.0f;
            w1p[j * 5 + cc] = pack2(a, bb);
        }
    }
    if (tid == 0) {
        #pragma unroll
        for (int s = 0; s < NSTAGE; s++) {
            MBARRIER_INIT(mb_bfull + 8 * s, 1);
            MBARRIER_INIT(mb_afull + 8 * s, 1);
            MBARRIER_INIT(mb_mdone + 8 * s, 1);
        }
        MBARRIER_INIT(mb_alldone, 1);
    }
    __syncthreads();

    uint32_t tmem;
    asm volatile("ld.shared.b32 %0, [%1];" : "=r"(tmem) : "r"(smem_base + SM_CTRL));

    if (wid == 0) {
        // =================== MMA issuer (warp 0) ===================
        int s = 0, ph = 0;
        for (int c = 0; c < NCHUNK; c++) {
            MBARRIER_WAIT_PARITY(mb_afull + 8 * s, ph);
            MBARRIER_WAIT_PARITY(mb_bfull + 8 * s, ph);
            if (elect_one_pred()) {
                TCGEN05_FENCE_AFTER();
                const uint32_t abase = smem_base + SM_A + s * 32768;
                uint64_t a0h = MAKE_SMEM_DESC64(abase);
                uint64_t a0l = MAKE_SMEM_DESC64(abase + 8192);
                uint64_t a1h = MAKE_SMEM_DESC64(abase + 16384);
                uint64_t a1l = MAKE_SMEM_DESC64(abase + 24576);
                uint64_t bh  = MAKE_SMEM_DESC64(smem_base + SM_B + s * 32768);
                uint64_t bl  = MAKE_SMEM_DESC64(smem_base + SM_B + s * 32768 + 16384);
                int nst = (c == NCHUNK - 1) ? 1 : 2;   // K=16 per MMA step
                for (int ks = 0; ks < nst; ks++) {
                    uint64_t o = (uint64_t)(ks * 2);   // +32B per 16 bf16
                    bool acc = !(c == 0 && ks == 0);
                    // tile 0 -> TMEM cols 0..255
                    mma_f16_ss(tmem,       a0h + o, bh + o, MMA_IDESC, acc);
                    mma_f16_ss(tmem,       a0h + o, bl + o, MMA_IDESC, true);
                    mma_f16_ss(tmem,       a0l + o, bh + o, MMA_IDESC, true);
                    // tile 1 -> TMEM cols 256..511
                    mma_f16_ss(tmem + 256, a1h + o, bh + o, MMA_IDESC, acc);
                    mma_f16_ss(tmem + 256, a1h + o, bl + o, MMA_IDESC, true);
                    mma_f16_ss(tmem + 256, a1l + o, bh + o, MMA_IDESC, true);
                }
                TCGEN05_COMMIT(mb_mdone + 8 * s);
                if (c == NCHUNK - 1) TCGEN05_COMMIT(mb_alldone);
            }
            if (++s == NSTAGE) { s = 0; ph ^= 1; }
        }
    } else {
        // ==================== loaders (warps 1-7) ====================
        const int ltid = tid - 32;   // 0..223

        // Phase 1: batch global loads for chunk c into registers (zero-filled).
        auto load_regs = [&](int c, float4* v) {
            const int kvalid = KPIX - c * BK;   // 32 except last chunk = 16
            #pragma unroll
            for (int i = 0; i < LPT; i++) {
                v[i] = make_float4(0.f, 0.f, 0.f, 0.f);
                int idx  = ltid + i * NLOAD;
                int row  = idx >> 3;       // 0..255
                int col4 = idx & 7;        // float4 within 32-col chunk
                if (idx < NF4 && col4 * 4 < kvalid) {
                    v[i] = *(const float4*)(
                        X + (long)(m0 + row) * KPIX + c * BK + col4 * 4);
                }
            }
        };
        // Phase 2: convert bf16 hi/lo + SW64 STS (always store; zeros pad).
        auto store_stage = [&](int s, const float4* v) {
            char* astage = smem + SM_A + s * 32768;
            #pragma unroll
            for (int i = 0; i < LPT; i++) {
                int idx  = ltid + i * NLOAD;
                int row  = idx >> 3;
                int col4 = idx & 7;
                if (idx < NF4) {
                    int tile = row >> 7;        // 0 or 1
                    int r1   = row & 127;
                    char* ahi = astage + tile * 16384;
                    char* alo = ahi + 8192;
                    __nv_bfloat16 h0 = __float2bfloat16_rn(v[i].x);
                    __nv_bfloat16 h1 = __float2bfloat16_rn(v[i].y);
                    __nv_bfloat16 h2 = __float2bfloat16_rn(v[i].z);
                    __nv_bfloat16 h3 = __float2bfloat16_rn(v[i].w);
                    __nv_bfloat16 l0 = __float2bfloat16_rn(v[i].x - __bfloat162float(h0));
                    __nv_bfloat16 l1 = __float2bfloat16_rn(v[i].y - __bfloat162float(h1));
                    __nv_bfloat16 l2 = __float2bfloat16_rn(v[i].z - __bfloat162float(h2));
                    __nv_bfloat16 l3 = __float2bfloat16_rn(v[i].w - __bfloat162float(h3));
                    __nv_bfloat162 hp0{h0, h1}, hp1{h2, h3};
                    __nv_bfloat162 lp0{l0, l1}, lp1{l2, l3};
                    uint2 hv, lv;
                    hv.x = *(uint32_t*)&hp0; hv.y = *(uint32_t*)&hp1;
                    lv.x = *(uint32_t*)&lp0; lv.y = *(uint32_t*)&lp1;
                    uint32_t sw = sw64((uint32_t)(r1 * 64 + col4 * 8));
                    *(uint2*)(ahi + sw) = hv;
                    *(uint2*)(alo + sw) = lv;
                }
            }
        };
        // All loader warps synced, then one thread arrives (afull count=1).
        auto publish = [&](int s) {
            FENCE_PROXY_ASYNC();
            asm volatile("bar.sync 1, %0;" :: "r"(NLOAD) : "memory");
            if (tid == 32) MBARRIER_ARRIVE(mb_afull + 8 * s);
        };
        auto b_copy = [&](int c, int s) {
            MBARRIER_EXPECT_TX(mb_bfull + 8 * s, 32768);
            CP_ASYNC_BULK_G2S(smem_base + SM_B + s * 32768,
                              (const void*)(g_B + c * BCHUNK_ELEMS),
                              32768, mb_bfull + 8 * s);
        };

        // prologue: fill all 3 stages (chunks 0..2)
        if (tid == 32) { b_copy(0, 0); b_copy(1, 1); b_copy(2, 2); }
        {
            float4 v[LPT];
            load_regs(0, v); store_stage(0, v); publish(0);
            load_regs(1, v); store_stage(1, v); publish(1);
            load_regs(2, v); store_stage(2, v); publish(2);
        }

        // main loop: chunk c reuses stage c%3 after MMA(c-3) completes.
        int sL = 0, phL = 0;
        for (int c = NSTAGE; c < NCHUNK; c++) {
            float4 v[LPT];
            load_regs(c, v);                     // overlaps the mdone wait
            MBARRIER_WAIT_PARITY(mb_mdone + 8 * sL, phL);
            if (tid == 32) b_copy(c, sL);
            store_stage(sL, v);
            publish(sL);
            if (++sL == NSTAGE) { sL = 0; phL ^= 1; }
        }
    }

    // ---- all threads: wait for every MMA to complete ----
    MBARRIER_WAIT_PARITY(mb_alldone, 0);
    __syncthreads();
    TCGEN05_FENCE_AFTER();

    // ---- fused epilogue: h = relu(D + b0); out = h @ w1T + b1 (both tiles)
    const int sub  = wid & 3;          // TMEM subpartition (rows sub*32..+31)
    const int half = wid >> 2;         // 0: cols 0..127, 1: cols 128..255
    const int r    = sub * 32 + lid;
    const float* b0s = (const float*)(smem + SM_B0);
    const unsigned long long* w1p = (const unsigned long long*)(smem + SM_W1P);
    float* outst = (float*)(smem + SM_OUT);   // A ring dead; 256 rows x 10

    #pragma unroll
    for (int t = 0; t < 2; t++) {
        unsigned long long p2[5] = {0, 0, 0, 0, 0};
        #pragma unroll
        for (int blk = 0; blk < 4; blk++) {
            uint32_t d[32];
            TCGEN05_LD_32X32B_X32(d, tmem + t * 256 + half * 128 + blk * 32);
            TCGEN05_WAIT_LD();
            #pragma unroll
            for (int i = 0; i < 32; i++) {
                int j = half * 128 + blk * 32 + i;
                float h = fmaxf(__uint_as_float(d[i]) + b0s[j], 0.0f);
                unsigned long long hh = pack2(h, h);
                #pragma unroll
                for (int cc = 0; cc < 5; cc++) fma2(p2[cc], hh, w1p[j * 5 + cc]);
            }
        }
        TCGEN05_FENCE_BEFORE();

        int rg = t * 128 + r;
        if (half == 0) {
            #pragma unroll
            for (int cc = 0; cc < 5; cc++) {
                float2 f = unpack2(p2[cc]);
                outst[rg * 10 + 2 * cc]     = f.x;
                outst[rg * 10 + 2 * cc + 1] = f.y;
            }
        }
        __syncthreads();
        if (half == 1) {
            long m = m0 + rg;
            #pragma unroll
            for (int cc = 0; cc < 5; cc++) {
                float2 f = unpack2(p2[cc]);
                out[m * NOUT + 2 * cc]     = outst[rg * 10 + 2 * cc]     + f.x + b1[2 * cc];
                out[m * NOUT + 2 * cc + 1] = outst[rg * 10 + 2 * cc + 1] + f.y + b1[2 * cc + 1];
            }
        }
        __syncthreads();
    }

    if (wid == 0) {
        TCGEN05_RELINQUISH();
        TCGEN05_DEALLOC(tmem, 512);
    }

#else  // ---------------- portable fallback (non-sm_103a passes) ------------
    extern __shared__ char smem[];
    const int tid = threadIdx.x;
    const int m0  = blockIdx.x * BM;
    // Each thread handles one of 256 rows entirely.
    const float* xr = X + (long)(m0 + tid) * KPIX;
    float o[NOUT];
    #pragma unroll
    for (int c = 0; c < NOUT; c++) o[c] = b1[c];
    for (int j = 0; j < HID; j++) {
        const float* wr = g_Weff + j * KPIX;
        float s = 0.0f;
        for (int k = 0; k < KPIX; k += 4) {
            float4 xv = *(const float4*)(xr + k);
            float4 wv = *(const float4*)(wr + k);
            s += xv.x * wv.x + xv.y * wv.y + xv.z * wv.z + xv.w * wv.w;
        }
        float h = fmaxf(s + b0[j], 0.0f);
        #pragma unroll
        for (int c = 0; c < NOUT; c++) o[c] += h * w1[c * HID + j];
    }
    #pragma unroll
    for (int c = 0; c < NOUT; c++) out[(long)(m0 + tid) * NOUT + c] = o[c];
#endif
}

// ---------------------------------------------------------------------------
// kernel_launch: graph-capturable, allocation-free.
// Inputs (metadata order): x, conv_w, w0, b0, w1, b1
// ---------------------------------------------------------------------------
extern "C" void kernel_launch(void* const* d_in, const int* in_sizes, int n_in,
                              void* d_out, int out_size) {
    const float* x      = (const float*)d_in[0];
    const float* conv_w = (const float*)d_in[1];
    const float* w0     = (const float*)d_in[2];
    const float* b0     = (const float*)d_in[3];
    const float* w1     = (const float*)d_in[4];
    const float* b1     = (const float*)d_in[5];
    float* out = (float*)d_out;

    cudaFuncSetAttribute(gemm_fused_kernel,
                         cudaFuncAttributeMaxDynamicSharedMemorySize, SMEM_TOTAL);

    build_weff_kernel<<<HPAD, NCHUNK * BK>>>(conv_w, w0);
    gemm_fused_kernel<<<BATCH / BM, GEMM_THREADS, SMEM_TOTAL>>>(x, b0, w1, b1, out);
}

// round 12
// speedup vs baseline: 1.2767x; 1.1688x over previous
#include <cuda_runtime.h>
#include <cuda_bf16.h>
#include <cstdint>

// ---------------------------------------------------------------------------
// Problem constants
// ---------------------------------------------------------------------------
#define BATCH   32768
#define IMG     28
#define KPIX    784      // GEMM K
#define OUT_HW  26
#define OPIX    676
#define HID     200
#define HPAD    256      // padded hidden (GEMM N)
#define NOUT    10

#define BM      128      // M rows per CTA
#define BK      64       // K per chunk (bf16 -> 128B rows, SW128)
#define NCHUNK  13       // 12*64 + 16
#define GEMM_THREADS 256
#define NLOAD   224      // loader threads (warps 1..7)
#define NUNIT   1024     // 8-float units per chunk (128 rows x 8)
#define LPU     5        // units per loader thread (224*5 >= 1024)

// idesc kind::f16 (bf16 in, fp32 acc), M=128, N=256
#define MMA_IDESC 0x8400490u

#if defined(__CUDA_ARCH__) && defined(__CUDA_ARCH_FEAT_SM103_ALL)
#define HAS_TCGEN05 1
#else
#define HAS_TCGEN05 0
#endif

// elements per B chunk block: [hi 256x64 | lo 256x64] = 32768 bf16 = 64KB
#define BCHUNK_ELEMS (2 * HPAD * BK)

// ---------------------------------------------------------------------------
// Global scratch.
//  g_B   : per chunk, 64KB contiguous [hi 32KB | lo 32KB], SW128 pre-swizzled
//  g_Weff: fp32 Weff for the portable fallback path (never runs on GB300)
// ---------------------------------------------------------------------------
__device__ __align__(16) __nv_bfloat16 g_B[NCHUNK * BCHUNK_ELEMS];
__device__ __align__(16) float         g_Weff[HPAD * KPIX];

// ---------------------------------------------------------------------------
// Arch-neutral helpers
// ---------------------------------------------------------------------------
__device__ __forceinline__ uint32_t smem_to_u32(const void* p) {
    uint32_t a;
    asm("{ .reg .u64 t; cvta.to.shared.u64 t, %1; cvt.u32.u64 %0, t; }"
        : "=r"(a) : "l"(p));
    return a;
}
__device__ __forceinline__ unsigned long long pack2(float lo, float hi) {
    unsigned long long r;
    asm("mov.b64 %0, {%1, %2};" : "=l"(r) : "f"(lo), "f"(hi));
    return r;
}
__device__ __forceinline__ void fma2(unsigned long long& d,
                                     unsigned long long a,
                                     unsigned long long b) {
    asm("fma.rn.f32x2 %0, %1, %2, %0;" : "+l"(d) : "l"(a), "l"(b));
}
__device__ __forceinline__ float2 unpack2(unsigned long long v) {
    float2 f;
    asm("mov.b64 {%0, %1}, %2;" : "=f"(f.x), "=f"(f.y) : "l"(v));
    return f;
}
// packed rn convert: returns [bf16(hi_) | bf16(lo_)] (hi_ in upper 16 bits)
__device__ __forceinline__ uint32_t cvt2bf(float hi_, float lo_) {
    uint32_t r;
    asm("cvt.rn.bf16x2.f32 %0, %1, %2;" : "=r"(r) : "f"(hi_), "f"(lo_));
    return r;
}

// SW128 swizzle (bits [6:4] ^= bits [9:7])
__host__ __device__ __forceinline__ uint32_t sw128(uint32_t off) {
    return off ^ ((off >> 3) & 0x70);
}

#if HAS_TCGEN05
// ---------------------------------------------------------------------------
// tcgen05 / mbarrier / bulk-copy PTX helpers (sm_103a-only compilation)
// ---------------------------------------------------------------------------
__device__ __forceinline__ uint32_t elect_one_pred() {
    uint32_t pred;
    asm volatile(
        "{\n\t.reg .pred p;\n\t"
        "elect.sync _|p, 0xFFFFFFFF;\n\t"
        "selp.b32 %0, 1, 0, p;\n\t}"
        : "=r"(pred));
    return pred;
}

#define MBARRIER_INIT(addr, cnt) \
    asm volatile("mbarrier.init.shared.b64 [%0], %1;" \
        :: "r"((uint32_t)(addr)), "r"((uint32_t)(cnt)) : "memory")

#define MBARRIER_ARRIVE(addr) \
    asm volatile("mbarrier.arrive.release.cta.shared::cta.b64 _, [%0];" \
        :: "r"((uint32_t)(addr)) : "memory")

#define MBARRIER_EXPECT_TX(addr, bytes) \
    asm volatile("mbarrier.arrive.expect_tx.shared.b64 _, [%0], %1;" \
        :: "r"((uint32_t)(addr)), "r"((uint32_t)(bytes)) : "memory")

#define MBARRIER_WAIT_PARITY(addr, par) do { \
    uint32_t _m = (uint32_t)(addr); \
    uint32_t _p = (uint32_t)(par); \
    uint32_t _done; \
    asm volatile( \
        "{\n\t.reg .pred p;\n\t" \
        "mbarrier.try_wait.parity.acquire.cta.shared::cta.b64 p, [%1], %2;\n\t" \
        "selp.b32 %0, 1, 0, p;\n\t}" \
        : "=r"(_done) : "r"(_m), "r"(_p) : "memory"); \
    if (!_done) { \
        asm volatile( \
            "{\n\t.reg .pred P1;\n\t" \
            "WAIT_LOOP_%=:\n\t" \
            "mbarrier.try_wait.parity.acquire.cta.shared::cta.b64 P1, [%0], %1, 0x989680;\n\t" \
            "@P1 bra.uni WAIT_DONE_%=;\n\t" \
            "bra.uni WAIT_LOOP_%=;\n\t" \
            "WAIT_DONE_%=:\n\t}" \
            :: "r"(_m), "r"(_p) : "memory"); \
    } \
} while (0)

// plain bulk copy gmem -> smem, completion via tx mbarrier (UBLKCP)
#define CP_ASYNC_BULK_G2S(dst, src, bytes, mbar) \
    asm volatile( \
        "cp.async.bulk.shared::cluster.global.mbarrier::complete_tx::bytes " \
        "[%0], [%1], %2, [%3];" \
        :: "r"((uint32_t)(dst)), "l"(src), "r"((uint32_t)(bytes)), \
           "r"((uint32_t)(mbar)) : "memory")

#define TCGEN05_ALLOC(res_addr, ncols) \
    asm volatile("tcgen05.alloc.cta_group::1.sync.aligned.shared::cta.b32 [%0], %1;" \
        :: "r"((uint32_t)(res_addr)), "r"((uint32_t)(ncols)) : "memory")
#define TCGEN05_DEALLOC(tmem, ncols) \
    asm volatile("tcgen05.dealloc.cta_group::1.sync.aligned.b32 %0, %1;" \
        :: "r"(tmem), "r"((uint32_t)(ncols)))
#define TCGEN05_RELINQUISH() \
    asm volatile("tcgen05.relinquish_alloc_permit.cta_group::1.sync.aligned;")
#define TCGEN05_COMMIT(mbar) \
    asm volatile("tcgen05.commit.cta_group::1.mbarrier::arrive::one.shared::cluster.b64 [%0];" \
        :: "r"((uint32_t)(mbar)) : "memory")
#define TCGEN05_WAIT_LD() \
    asm volatile("tcgen05.wait::ld.sync.aligned;" ::: "memory")
#define TCGEN05_FENCE_BEFORE() \
    asm volatile("tcgen05.fence::before_thread_sync;" ::: "memory")
#define TCGEN05_FENCE_AFTER() \
    asm volatile("tcgen05.fence::after_thread_sync;" ::: "memory")
#define FENCE_PROXY_ASYNC() \
    asm volatile("fence.proxy.async.shared::cta;" ::: "memory")

#define TCGEN05_LD_32X32B_X32(r, tmem_addr) \
    asm volatile( \
        "tcgen05.ld.sync.aligned.32x32b.x32.b32 " \
        "{%0, %1, %2, %3, %4, %5, %6, %7, " \
        " %8, %9, %10, %11, %12, %13, %14, %15, " \
        " %16, %17, %18, %19, %20, %21, %22, %23, " \
        " %24, %25, %26, %27, %28, %29, %30, %31}, [%32];" \
        : "=r"((r)[0]),  "=r"((r)[1]),  "=r"((r)[2]),  "=r"((r)[3]), \
          "=r"((r)[4]),  "=r"((r)[5]),  "=r"((r)[6]),  "=r"((r)[7]), \
          "=r"((r)[8]),  "=r"((r)[9]),  "=r"((r)[10]), "=r"((r)[11]), \
          "=r"((r)[12]), "=r"((r)[13]), "=r"((r)[14]), "=r"((r)[15]), \
          "=r"((r)[16]), "=r"((r)[17]), "=r"((r)[18]), "=r"((r)[19]), \
          "=r"((r)[20]), "=r"((r)[21]), "=r"((r)[22]), "=r"((r)[23]), \
          "=r"((r)[24]), "=r"((r)[25]), "=r"((r)[26]), "=r"((r)[27]), \
          "=r"((r)[28]), "=r"((r)[29]), "=r"((r)[30]), "=r"((r)[31]) \
        : "r"(tmem_addr))

// SW128 K-major descriptor base (LBO=1, SBO=64, version=1, layout=SW128)
static constexpr uint64_t SMEM_DESC_BASE_SW128 =
    (uint64_t(2)  << 61) | (uint64_t(1) << 46) |
    (uint64_t(64) << 32) | (uint64_t(1) << 16);
#define MAKE_SMEM_DESC(addr) \
    (SMEM_DESC_BASE_SW128 | ((uint64_t)((addr) >> 4) & 0x3FFF))

__device__ __forceinline__ void mma_f16_ss(uint32_t d_tmem, uint64_t a_desc,
                                           uint64_t b_desc, uint32_t idesc,
                                           bool acc) {
    uint32_t en = acc ? 1u : 0u;
    asm volatile(
        "{\n\t.reg .pred p;\n\t"
        "setp.ne.u32 p, %5, 0;\n\t"
        "tcgen05.mma.cta_group::1.kind::f16 [%0], %1, %2, %3, "
        "{%4, %4, %4, %4}, p;\n\t}"
        :: "r"(d_tmem), "l"(a_desc), "l"(b_desc), "r"(idesc),
           "r"(0u), "r"(en)
        : "memory");
}
#endif // HAS_TCGEN05

// ---------------------------------------------------------------------------
// Kernel 1: fold conv into w0; write fp32 g_Weff (fallback) and SW128
// pre-swizzled bf16 hi/lo chunk blocks g_B. grid=HPAD, block=832 (13*64).
// ---------------------------------------------------------------------------
__global__ void build_weff_kernel(const float* __restrict__ conv_w,
                                  const float* __restrict__ w0) {
    int j = blockIdx.x;      // hidden unit 0..255
    int p = threadIdx.x;     // k position 0..831
    float s = 0.0f;
    if (j < HID && p < KPIX) {
        int py = p / IMG, px = p % IMG;
        #pragma unroll
        for (int ky = 0; ky < 3; ky++)
            #pragma unroll
            for (int kx = 0; kx < 3; kx++) {
                int oy = py - ky, ox = px - kx;
                if (oy >= 0 && oy < OUT_HW && ox >= 0 && ox < OUT_HW)
                    s += conv_w[ky * 3 + kx] * w0[j * OPIX + oy * OUT_HW + ox];
            }
    }
    if (p < KPIX) g_Weff[j * KPIX + p] = s;

    __nv_bfloat16 hi = __float2bfloat16_rn(s);
    __nv_bfloat16 lo = __float2bfloat16_rn(s - __bfloat162float(hi));
    int chunk = p >> 6, kin = p & 63;                // BK=64
    uint32_t off = (uint32_t)(j * 128 + kin * 2);    // bytes within 32KB tile
    uint32_t sw  = sw128(off);
    int base = chunk * BCHUNK_ELEMS;                 // [hi 16384 | lo 16384]
    g_B[base + (int)(sw >> 1)]             = hi;
    g_B[base + HPAD * BK + (int)(sw >> 1)] = lo;
}

// ---------------------------------------------------------------------------
// Kernel 2: fused  out = relu(X @ WeffT + b0) @ w1T + b1  (tcgen05, 2-way
// bf16 split). R12 loader fixes: cross-chunk double-buffered LDGs (latency
// hidden), STS.128 + packed cvt (half the fence drain), per-warp fence +
// mbarrier arrive count=7 (no CTA-wide bar.sync).
// ---------------------------------------------------------------------------
// smem byte offsets
// ctrl: tmem ptr @0; bfull @16/24; afull @32/40; mdone @48/56; alldone @64
#define SM_CTRL   0
#define SM_A      1024       // 2 stages x (hi 16KB | lo 16KB) = 65536
#define SM_B      66560      // 2 stages x (hi 32KB | lo 32KB) = 131072
#define SM_W1P    197632     // 256*5*8 = 10240
#define SM_B0     207872     // 1024
#define SM_OUT    208896     // 128*10*4 = 5120
#define SMEM_TOTAL 214016

__global__ void __launch_bounds__(GEMM_THREADS, 1)
gemm_fused_kernel(const float* __restrict__ X,
                  const float* __restrict__ b0,
                  const float* __restrict__ w1,
                  const float* __restrict__ b1,
                  float* __restrict__ out) {
#if HAS_TCGEN05
    extern __shared__ char smem[];
    const uint32_t smem_base = smem_to_u32(smem);
    const int tid = threadIdx.x;
    const int wid = tid >> 5;
    const int lid = tid & 31;
    const int m0  = blockIdx.x * BM;

    const uint32_t mb_bfull0  = smem_base + SM_CTRL + 16;
    const uint32_t mb_bfull1  = smem_base + SM_CTRL + 24;
    const uint32_t mb_afull0  = smem_base + SM_CTRL + 32;
    const uint32_t mb_afull1  = smem_base + SM_CTRL + 40;
    const uint32_t mb_mdone0  = smem_base + SM_CTRL + 48;
    const uint32_t mb_mdone1  = smem_base + SM_CTRL + 56;
    const uint32_t mb_alldone = smem_base + SM_CTRL + 64;

    // TMEM alloc (warp 0, collective): 256 fp32 accumulator columns
    if (wid == 0) TCGEN05_ALLOC(smem_base + SM_CTRL, 256);

    // epilogue weights into smem + mbarrier init
    if (tid < HPAD) {
        int j = tid;
        float* b0s = (float*)(smem + SM_B0);
        b0s[j] = (j < HID) ? b0[j] : 0.0f;
        unsigned long long* w1p = (unsigned long long*)(smem + SM_W1P);
        #pragma unroll
        for (int cc = 0; cc < 5; cc++) {
            float a  = (j < HID) ? w1[(2 * cc) * HID + j] : 0.0f;
            float bb = (j < HID) ? w1[(2 * cc + 1) * HID + j] : 0.0f;
            w1p[j * 5 + cc] = pack2(a, bb);
        }
    }
    if (tid == 0) {
        MBARRIER_INIT(mb_bfull0, 1);
        MBARRIER_INIT(mb_bfull1, 1);
        MBARRIER_INIT(mb_afull0, 7);   // one arrive per loader warp
        MBARRIER_INIT(mb_afull1, 7);
        MBARRIER_INIT(mb_mdone0, 1);
        MBARRIER_INIT(mb_mdone1, 1);
        MBARRIER_INIT(mb_alldone, 1);
    }
    __syncthreads();

    uint32_t tmem;
    asm volatile("ld.shared.b32 %0, [%1];" : "=r"(tmem) : "r"(smem_base + SM_CTRL));

    if (wid == 0) {
        // =================== MMA issuer (warp 0) ===================
        int phA0 = 0, phA1 = 0, phB0 = 0, phB1 = 0;
        for (int c = 0; c < NCHUNK; c++) {
            const int b = c & 1;
            if (b == 0) {
                MBARRIER_WAIT_PARITY(mb_afull0, phA0); phA0 ^= 1;
                MBARRIER_WAIT_PARITY(mb_bfull0, phB0); phB0 ^= 1;
            } else {
                MBARRIER_WAIT_PARITY(mb_afull1, phA1); phA1 ^= 1;
                MBARRIER_WAIT_PARITY(mb_bfull1, phB1); phB1 ^= 1;
            }
            if (elect_one_pred()) {
                TCGEN05_FENCE_AFTER();
                uint64_t ah = MAKE_SMEM_DESC(smem_base + SM_A + b * 32768);
                uint64_t al = MAKE_SMEM_DESC(smem_base + SM_A + b * 32768 + 16384);
                uint64_t bh = MAKE_SMEM_DESC(smem_base + SM_B + b * 65536);
                uint64_t bl = MAKE_SMEM_DESC(smem_base + SM_B + b * 65536 + 32768);
                int nst = (c == NCHUNK - 1) ? 1 : 4;   // K=16 per MMA step
                for (int ks = 0; ks < nst; ks++) {
                    uint64_t o = (uint64_t)(ks * 2);   // +32B per 16 bf16
                    mma_f16_ss(tmem, ah + o, bh + o, MMA_IDESC, !(c == 0 && ks == 0));
                    mma_f16_ss(tmem, ah + o, bl + o, MMA_IDESC, true);
                    mma_f16_ss(tmem, al + o, bh + o, MMA_IDESC, true);
                }
                TCGEN05_COMMIT(b == 0 ? mb_mdone0 : mb_mdone1);
                if (c == NCHUNK - 1) TCGEN05_COMMIT(mb_alldone);
            }
        }
    } else {
        // ==================== loaders (warps 1-7) ====================
        const int ltid = tid - 32;   // 0..223

        // Unit = 8 consecutive f32 (32B) -> one STS.128 hi + one STS.128 lo.
        float4 vA[2 * LPU], vB[2 * LPU];   // double buffers (chunk parity)

        auto load_unit = [&](int c, float4* v) {
            const int kvalid = KPIX - c * BK;      // 64 except last = 16
            #pragma unroll
            for (int i = 0; i < LPU; i++) {
                int u    = ltid + i * NLOAD;
                int row  = u >> 3;
                int ucol = u & 7;
                v[2 * i]     = make_float4(0.f, 0.f, 0.f, 0.f);
                v[2 * i + 1] = make_float4(0.f, 0.f, 0.f, 0.f);
                if (u < NUNIT && ucol * 8 < kvalid) {
                    const float* p = X + (long)(m0 + row) * KPIX + c * BK + ucol * 8;
                    v[2 * i]     = *(const float4*)p;
                    v[2 * i + 1] = *(const float4*)(p + 4);
                }
            }
        };

        auto store_stage = [&](int s, const float4* v) {
            char* ahi = smem + SM_A + s * 32768;
            char* alo = ahi + 16384;
            #pragma unroll
            for (int i = 0; i < LPU; i++) {
                int u    = ltid + i * NLOAD;
                int row  = u >> 3;
                int ucol = u & 7;
                if (u < NUNIT) {
                    float f0 = v[2*i].x,   f1 = v[2*i].y;
                    float f2 = v[2*i].z,   f3 = v[2*i].w;
                    float f4_ = v[2*i+1].x, f5 = v[2*i+1].y;
                    float f6 = v[2*i+1].z, f7 = v[2*i+1].w;
                    uint32_t h01 = cvt2bf(f1, f0);
                    uint32_t h23 = cvt2bf(f3, f2);
                    uint32_t h45 = cvt2bf(f5, f4_);
                    uint32_t h67 = cvt2bf(f7, f6);
                    float e0 = f0 - __int_as_float(h01 << 16);
                    float e1 = f1 - __int_as_float(h01 & 0xFFFF0000u);
                    float e2 = f2 - __int_as_float(h23 << 16);
                    float e3 = f3 - __int_as_float(h23 & 0xFFFF0000u);
                    float e4 = f4_ - __int_as_float(h45 << 16);
                    float e5 = f5 - __int_as_float(h45 & 0xFFFF0000u);
                    float e6 = f6 - __int_as_float(h67 << 16);
                    float e7 = f7 - __int_as_float(h67 & 0xFFFF0000u);
                    uint32_t l01 = cvt2bf(e1, e0);
                    uint32_t l23 = cvt2bf(e3, e2);
                    uint32_t l45 = cvt2bf(e5, e4);
                    uint32_t l67 = cvt2bf(e7, e6);
                    uint32_t sw = sw128((uint32_t)(row * 128 + ucol * 16));
                    *(uint4*)(ahi + sw) = make_uint4(h01, h23, h45, h67);
                    *(uint4*)(alo + sw) = make_uint4(l01, l23, l45, l67);
                }
            }
        };

        // per-warp fence + single-lane arrive (afull count = 7)
        auto publish = [&](uint32_t mbar) {
            FENCE_PROXY_ASYNC();
            __syncwarp();
            if (lid == 0) MBARRIER_ARRIVE(mbar);
        };
        auto b_copy = [&](int c, uint32_t mbar, int s) {
            MBARRIER_EXPECT_TX(mbar, 65536);
            CP_ASYNC_BULK_G2S(smem_base + SM_B + s * 65536,
                              (const void*)(g_B + c * BCHUNK_ELEMS),
                              65536, mbar);
        };

        // prologue: B copies for 0,1; A loads for 0..3 (double-buffered)
        if (tid == 32) { b_copy(0, mb_bfull0, 0); b_copy(1, mb_bfull1, 1); }
        load_unit(0, vA);
        load_unit(1, vB);
        store_stage(0, vA);
        publish(mb_afull0);
        load_unit(2, vA);             // in flight during chunk-1 store
        store_stage(1, vB);
        publish(mb_afull1);
        load_unit(3, vB);             // in flight during mainloop entry

        // main loop: chunk c's data was loaded one iteration ago.
        int phM0 = 0, phM1 = 0;
        for (int c = 2; c < NCHUNK; c++) {
            const int s = c & 1;
            if (s == 0) { MBARRIER_WAIT_PARITY(mb_mdone0, phM0); phM0 ^= 1; }
            else        { MBARRIER_WAIT_PARITY(mb_mdone1, phM1); phM1 ^= 1; }
            if (tid == 32) b_copy(c, s == 0 ? mb_bfull0 : mb_bfull1, s);
            store_stage(s, s == 0 ? vA : vB);
            if (c + 2 < NCHUNK) load_unit(c + 2, s == 0 ? vA : vB);
            publish(s == 0 ? mb_afull0 : mb_afull1);
        }
    }

    // ---- all threads: wait for every MMA to complete ----
    MBARRIER_WAIT_PARITY(mb_alldone, 0);
    __syncthreads();
    TCGEN05_FENCE_AFTER();

    // ---- fused epilogue: h = relu(D + b0); out = h @ w1T + b1 ----
    const int sub  = wid & 3;          // TMEM subpartition (rows sub*32..+31)
    const int half = wid >> 2;         // 0: cols 0..127, 1: cols 128..255
    const int r    = sub * 32 + lid;
    const float* b0s = (const float*)(smem + SM_B0);
    const unsigned long long* w1p = (const unsigned long long*)(smem + SM_W1P);

    unsigned long long p2[5] = {0, 0, 0, 0, 0};
    #pragma unroll
    for (int blk = 0; blk < 4; blk++) {
        uint32_t d[32];
        TCGEN05_LD_32X32B_X32(d, tmem + half * 128 + blk * 32);
        TCGEN05_WAIT_LD();
        #pragma unroll
        for (int i = 0; i < 32; i++) {
            int j = half * 128 + blk * 32 + i;
            float h = fmaxf(__uint_as_float(d[i]) + b0s[j], 0.0f);
            unsigned long long hh = pack2(h, h);
            #pragma unroll
            for (int cc = 0; cc < 5; cc++) fma2(p2[cc], hh, w1p[j * 5 + cc]);
        }
    }
    TCGEN05_FENCE_BEFORE();

    float* outst = (float*)(smem + SM_OUT);
    if (half == 0) {
        #pragma unroll
        for (int cc = 0; cc < 5; cc++) {
            float2 f = unpack2(p2[cc]);
            outst[r * 10 + 2 * cc]     = f.x;
            outst[r * 10 + 2 * cc + 1] = f.y;
        }
    }
    __syncthreads();
    if (half == 1) {
        long m = m0 + r;
        #pragma unroll
        for (int cc = 0; cc < 5; cc++) {
            float2 f = unpack2(p2[cc]);
            out[m * NOUT + 2 * cc]     = outst[r * 10 + 2 * cc]     + f.x + b1[2 * cc];
            out[m * NOUT + 2 * cc + 1] = outst[r * 10 + 2 * cc + 1] + f.y + b1[2 * cc + 1];
        }
    }
    __syncthreads();

    if (wid == 0) {
        TCGEN05_RELINQUISH();
        TCGEN05_DEALLOC(tmem, 256);
    }

#else  // ---------------- portable fallback (non-sm_103a passes) ------------
    extern __shared__ char smem[];
    const int tid  = threadIdx.x;
    const int r    = tid & 127;
    const int half = tid >> 7;
    const int m0   = blockIdx.x * BM;
    float* hbuf = (float*)smem;

    const float* xr = X + (long)(m0 + r) * KPIX;
    for (int j = half * 100; j < half * 100 + 100; j++) {
        const float* wr = g_Weff + j * KPIX;
        float s = 0.0f;
        for (int k = 0; k < KPIX; k += 4) {
            float4 xv = *(const float4*)(xr + k);
            float4 wv = *(const float4*)(wr + k);
            s += xv.x * wv.x + xv.y * wv.y + xv.z * wv.z + xv.w * wv.w;
        }
        hbuf[r * HID + j] = fmaxf(s + b0[j], 0.0f);
    }
    __syncthreads();
    if (half == 0) {
        float o[NOUT];
        #pragma unroll
        for (int c = 0; c < NOUT; c++) o[c] = b1[c];
        for (int j = 0; j < HID; j++) {
            float h = hbuf[r * HID + j];
            #pragma unroll
            for (int c = 0; c < NOUT; c++) o[c] += h * w1[c * HID + j];
        }
        #pragma unroll
        for (int c = 0; c < NOUT; c++) out[(long)(m0 + r) * NOUT + c] = o[c];
    }
#endif
}

// ---------------------------------------------------------------------------
// kernel_launch: graph-capturable, allocation-free.
// Inputs (metadata order): x, conv_w, w0, b0, w1, b1
// ---------------------------------------------------------------------------
extern "C" void kernel_launch(void* const* d_in, const int* in_sizes, int n_in,
                              void* d_out, int out_size) {
    const float* x      = (const float*)d_in[0];
    const float* conv_w = (const float*)d_in[1];
    const float* w0     = (const float*)d_in[2];
    const float* b0     = (const float*)d_in[3];
    const float* w1     = (const float*)d_in[4];
    const float* b1     = (const float*)d_in[5];
    float* out = (float*)d_out;

    cudaFuncSetAttribute(gemm_fused_kernel,
                         cudaFuncAttributeMaxDynamicSharedMemorySize, SMEM_TOTAL);

    build_weff_kernel<<<HPAD, NCHUNK * BK>>>(conv_w, w0);
    gemm_fused_kernel<<<BATCH / BM, GEMM_THREADS, SMEM_TOTAL>>>(x, b0, w1, b1, out);
}

// round 13
// speedup vs baseline: 1.6212x; 1.2699x over previous
#include <cuda_runtime.h>
#include <cuda_fp16.h>
#include <cstdint>

// ---------------------------------------------------------------------------
// Problem constants
// ---------------------------------------------------------------------------
#define BATCH   32768
#define IMG     28
#define KPIX    784      // GEMM K
#define OUT_HW  26
#define OPIX    676
#define HID     200
#define HPAD    256      // padded hidden (GEMM N)
#define NOUT    10

#define BM      128      // M rows per CTA
#define BK      64       // K per chunk (fp16 -> 128B rows, SW128)
#define NCHUNK  13       // 12*64 + 16
#define NSTAGE  3        // ring depth (48KB/stage now)
#define GEMM_THREADS 256
#define NLOAD   224      // loader threads (warps 1..7)
#define NUNIT   1024     // 8-float units per chunk (128 rows x 8)
#define LPU     5        // units per loader thread (224*5 >= 1024)

// idesc kind::f16 (fp16 in, fp32 acc), M=128, N=256:
//   dtype F32 (1<<4) | atype F16 (0<<7) | btype F16 (0<<10)
//   | (N/8)<<17 | (M/16)<<24
#define MMA_IDESC 0x8400010u

#if defined(__CUDA_ARCH__) && defined(__CUDA_ARCH_FEAT_SM103_ALL)
#define HAS_TCGEN05 1
#else
#define HAS_TCGEN05 0
#endif

// elements per B chunk block: 256 x 64 fp16 = 16384 halves = 32KB
#define BCHUNK_ELEMS (HPAD * BK)

// ---------------------------------------------------------------------------
// Global scratch.
//  g_B   : per chunk, 32KB SW128 pre-swizzled fp16 Weff tile
//  g_Weff: fp32 Weff for the portable fallback path (never runs on GB300)
// ---------------------------------------------------------------------------
__device__ __align__(16) __half g_B[NCHUNK * BCHUNK_ELEMS];
__device__ __align__(16) float  g_Weff[HPAD * KPIX];

// ---------------------------------------------------------------------------
// Arch-neutral helpers
// ---------------------------------------------------------------------------
__device__ __forceinline__ uint32_t smem_to_u32(const void* p) {
    uint32_t a;
    asm("{ .reg .u64 t; cvta.to.shared.u64 t, %1; cvt.u32.u64 %0, t; }"
        : "=r"(a) : "l"(p));
    return a;
}
__device__ __forceinline__ unsigned long long pack2(float lo, float hi) {
    unsigned long long r;
    asm("mov.b64 %0, {%1, %2};" : "=l"(r) : "f"(lo), "f"(hi));
    return r;
}
__device__ __forceinline__ void fma2(unsigned long long& d,
                                     unsigned long long a,
                                     unsigned long long b) {
    asm("fma.rn.f32x2 %0, %1, %2, %0;" : "+l"(d) : "l"(a), "l"(b));
}
__device__ __forceinline__ float2 unpack2(unsigned long long v) {
    float2 f;
    asm("mov.b64 {%0, %1}, %2;" : "=f"(f.x), "=f"(f.y) : "l"(v));
    return f;
}
// packed rn convert: returns [fp16(hi_) | fp16(lo_)] (hi_ in upper 16 bits)
__device__ __forceinline__ uint32_t cvt2h(float hi_, float lo_) {
    uint32_t r;
    asm("cvt.rn.f16x2.f32 %0, %1, %2;" : "=r"(r) : "f"(hi_), "f"(lo_));
    return r;
}

// SW128 swizzle (bits [6:4] ^= bits [9:7])
__host__ __device__ __forceinline__ uint32_t sw128(uint32_t off) {
    return off ^ ((off >> 3) & 0x70);
}

#if HAS_TCGEN05
// ---------------------------------------------------------------------------
// tcgen05 / mbarrier / bulk-copy PTX helpers (sm_103a-only compilation)
// ---------------------------------------------------------------------------
__device__ __forceinline__ uint32_t elect_one_pred() {
    uint32_t pred;
    asm volatile(
        "{\n\t.reg .pred p;\n\t"
        "elect.sync _|p, 0xFFFFFFFF;\n\t"
        "selp.b32 %0, 1, 0, p;\n\t}"
        : "=r"(pred));
    return pred;
}

#define MBARRIER_INIT(addr, cnt) \
    asm volatile("mbarrier.init.shared.b64 [%0], %1;" \
        :: "r"((uint32_t)(addr)), "r"((uint32_t)(cnt)) : "memory")

#define MBARRIER_ARRIVE(addr) \
    asm volatile("mbarrier.arrive.release.cta.shared::cta.b64 _, [%0];" \
        :: "r"((uint32_t)(addr)) : "memory")

#define MBARRIER_EXPECT_TX(addr, bytes) \
    asm volatile("mbarrier.arrive.expect_tx.shared.b64 _, [%0], %1;" \
        :: "r"((uint32_t)(addr)), "r"((uint32_t)(bytes)) : "memory")

#define MBARRIER_WAIT_PARITY(addr, par) do { \
    uint32_t _m = (uint32_t)(addr); \
    uint32_t _p = (uint32_t)(par); \
    uint32_t _done; \
    asm volatile( \
        "{\n\t.reg .pred p;\n\t" \
        "mbarrier.try_wait.parity.acquire.cta.shared::cta.b64 p, [%1], %2;\n\t" \
        "selp.b32 %0, 1, 0, p;\n\t}" \
        : "=r"(_done) : "r"(_m), "r"(_p) : "memory"); \
    if (!_done) { \
        asm volatile( \
            "{\n\t.reg .pred P1;\n\t" \
            "WAIT_LOOP_%=:\n\t" \
            "mbarrier.try_wait.parity.acquire.cta.shared::cta.b64 P1, [%0], %1, 0x989680;\n\t" \
            "@P1 bra.uni WAIT_DONE_%=;\n\t" \
            "bra.uni WAIT_LOOP_%=;\n\t" \
            "WAIT_DONE_%=:\n\t}" \
            :: "r"(_m), "r"(_p) : "memory"); \
    } \
} while (0)

// plain bulk copy gmem -> smem, completion via tx mbarrier (UBLKCP)
#define CP_ASYNC_BULK_G2S(dst, src, bytes, mbar) \
    asm volatile( \
        "cp.async.bulk.shared::cluster.global.mbarrier::complete_tx::bytes " \
        "[%0], [%1], %2, [%3];" \
        :: "r"((uint32_t)(dst)), "l"(src), "r"((uint32_t)(bytes)), \
           "r"((uint32_t)(mbar)) : "memory")

#define TCGEN05_ALLOC(res_addr, ncols) \
    asm volatile("tcgen05.alloc.cta_group::1.sync.aligned.shared::cta.b32 [%0], %1;" \
        :: "r"((uint32_t)(res_addr)), "r"((uint32_t)(ncols)) : "memory")
#define TCGEN05_DEALLOC(tmem, ncols) \
    asm volatile("tcgen05.dealloc.cta_group::1.sync.aligned.b32 %0, %1;" \
        :: "r"(tmem), "r"((uint32_t)(ncols)))
#define TCGEN05_RELINQUISH() \
    asm volatile("tcgen05.relinquish_alloc_permit.cta_group::1.sync.aligned;")
#define TCGEN05_COMMIT(mbar) \
    asm volatile("tcgen05.commit.cta_group::1.mbarrier::arrive::one.shared::cluster.b64 [%0];" \
        :: "r"((uint32_t)(mbar)) : "memory")
#define TCGEN05_WAIT_LD() \
    asm volatile("tcgen05.wait::ld.sync.aligned;" ::: "memory")
#define TCGEN05_FENCE_BEFORE() \
    asm volatile("tcgen05.fence::before_thread_sync;" ::: "memory")
#define TCGEN05_FENCE_AFTER() \
    asm volatile("tcgen05.fence::after_thread_sync;" ::: "memory")
#define FENCE_PROXY_ASYNC() \
    asm volatile("fence.proxy.async.shared::cta;" ::: "memory")

#define TCGEN05_LD_32X32B_X32(r, tmem_addr) \
    asm volatile( \
        "tcgen05.ld.sync.aligned.32x32b.x32.b32 " \
        "{%0, %1, %2, %3, %4, %5, %6, %7, " \
        " %8, %9, %10, %11, %12, %13, %14, %15, " \
        " %16, %17, %18, %19, %20, %21, %22, %23, " \
        " %24, %25, %26, %27, %28, %29, %30, %31}, [%32];" \
        : "=r"((r)[0]),  "=r"((r)[1]),  "=r"((r)[2]),  "=r"((r)[3]), \
          "=r"((r)[4]),  "=r"((r)[5]),  "=r"((r)[6]),  "=r"((r)[7]), \
          "=r"((r)[8]),  "=r"((r)[9]),  "=r"((r)[10]), "=r"((r)[11]), \
          "=r"((r)[12]), "=r"((r)[13]), "=r"((r)[14]), "=r"((r)[15]), \
          "=r"((r)[16]), "=r"((r)[17]), "=r"((r)[18]), "=r"((r)[19]), \
          "=r"((r)[20]), "=r"((r)[21]), "=r"((r)[22]), "=r"((r)[23]), \
          "=r"((r)[24]), "=r"((r)[25]), "=r"((r)[26]), "=r"((r)[27]), \
          "=r"((r)[28]), "=r"((r)[29]), "=r"((r)[30]), "=r"((r)[31]) \
        : "r"(tmem_addr))

// SW128 K-major descriptor base (LBO=1, SBO=64, version=1, layout=SW128)
static constexpr uint64_t SMEM_DESC_BASE_SW128 =
    (uint64_t(2)  << 61) | (uint64_t(1) << 46) |
    (uint64_t(64) << 32) | (uint64_t(1) << 16);
#define MAKE_SMEM_DESC(addr) \
    (SMEM_DESC_BASE_SW128 | ((uint64_t)((addr) >> 4) & 0x3FFF))

__device__ __forceinline__ void mma_f16_ss(uint32_t d_tmem, uint64_t a_desc,
                                           uint64_t b_desc, uint32_t idesc,
                                           bool acc) {
    uint32_t en = acc ? 1u : 0u;
    asm volatile(
        "{\n\t.reg .pred p;\n\t"
        "setp.ne.u32 p, %5, 0;\n\t"
        "tcgen05.mma.cta_group::1.kind::f16 [%0], %1, %2, %3, "
        "{%4, %4, %4, %4}, p;\n\t}"
        :: "r"(d_tmem), "l"(a_desc), "l"(b_desc), "r"(idesc),
           "r"(0u), "r"(en)
        : "memory");
}
#endif // HAS_TCGEN05

// ---------------------------------------------------------------------------
// Kernel 1: fold conv into w0; write fp32 g_Weff (fallback) and SW128
// pre-swizzled fp16 chunk tiles g_B. grid=HPAD, block=832 (13*64).
// ---------------------------------------------------------------------------
__global__ void build_weff_kernel(const float* __restrict__ conv_w,
                                  const float* __restrict__ w0) {
    int j = blockIdx.x;      // hidden unit 0..255
    int p = threadIdx.x;     // k position 0..831
    float s = 0.0f;
    if (j < HID && p < KPIX) {
        int py = p / IMG, px = p % IMG;
        #pragma unroll
        for (int ky = 0; ky < 3; ky++)
            #pragma unroll
            for (int kx = 0; kx < 3; kx++) {
                int oy = py - ky, ox = px - kx;
                if (oy >= 0 && oy < OUT_HW && ox >= 0 && ox < OUT_HW)
                    s += conv_w[ky * 3 + kx] * w0[j * OPIX + oy * OUT_HW + ox];
            }
    }
    if (p < KPIX) g_Weff[j * KPIX + p] = s;

    int chunk = p >> 6, kin = p & 63;                // BK=64
    uint32_t off = (uint32_t)(j * 128 + kin * 2);    // bytes within 32KB tile
    uint32_t sw  = sw128(off);
    g_B[chunk * BCHUNK_ELEMS + (int)(sw >> 1)] = __float2half_rn(s);
}

// ---------------------------------------------------------------------------
// Kernel 2: fused  out = relu(X @ WeffT + b0) @ w1T + b1  (tcgen05 fp16,
// single MMA per K-step). SMEM traffic per chunk cut 2.5x vs bf16-split:
// A 16KB STS + B 32KB TMA + 48KB MMA reads. 3-stage ring, warp-specialized.
// ---------------------------------------------------------------------------
// smem byte offsets
// ctrl: tmem ptr @0; bfull[3] @16..39; afull[3] @48..71; mdone[3] @80..103;
//       alldone @112
#define SM_CTRL   0
#define SM_A      1024       // 3 stages x 16KB = 49152
#define SM_B      50176      // 3 stages x 32KB = 98304
#define SM_W1P    148480     // 256*5*8 = 10240
#define SM_B0     158720     // 1024
#define SM_OUT    159744     // 128*10*4 = 5120
#define SMEM_TOTAL 164864

__global__ void __launch_bounds__(GEMM_THREADS, 1)
gemm_fused_kernel(const float* __restrict__ X,
                  const float* __restrict__ b0,
                  const float* __restrict__ w1,
                  const float* __restrict__ b1,
                  float* __restrict__ out) {
#if HAS_TCGEN05
    extern __shared__ char smem[];
    const uint32_t smem_base = smem_to_u32(smem);
    const int tid = threadIdx.x;
    const int wid = tid >> 5;
    const int lid = tid & 31;
    const int m0  = blockIdx.x * BM;

    const uint32_t mb_bfull   = smem_base + SM_CTRL + 16;  // +8*s
    const uint32_t mb_afull   = smem_base + SM_CTRL + 48;  // +8*s
    const uint32_t mb_mdone   = smem_base + SM_CTRL + 80;  // +8*s
    const uint32_t mb_alldone = smem_base + SM_CTRL + 112;

    // TMEM alloc (warp 0, collective): 256 fp32 accumulator columns
    if (wid == 0) TCGEN05_ALLOC(smem_base + SM_CTRL, 256);

    // epilogue weights into smem + mbarrier init
    if (tid < HPAD) {
        int j = tid;
        float* b0s = (float*)(smem + SM_B0);
        b0s[j] = (j < HID) ? b0[j] : 0.0f;
        unsigned long long* w1p = (unsigned long long*)(smem + SM_W1P);
        #pragma unroll
        for (int cc = 0; cc < 5; cc++) {
            float a  = (j < HID) ? w1[(2 * cc) * HID + j] : 0.0f;
            float bb = (j < HID) ? w1[(2 * cc + 1) * HID + j] : 0.0f;
            w1p[j * 5 + cc] = pack2(a, bb);
        }
    }
    if (tid == 0) {
        #pragma unroll
        for (int s = 0; s < NSTAGE; s++) {
            MBARRIER_INIT(mb_bfull + 8 * s, 1);
            MBARRIER_INIT(mb_afull + 8 * s, 7);   // one arrive per loader warp
            MBARRIER_INIT(mb_mdone + 8 * s, 1);
        }
        MBARRIER_INIT(mb_alldone, 1);
    }
    __syncthreads();

    uint32_t tmem;
    asm volatile("ld.shared.b32 %0, [%1];" : "=r"(tmem) : "r"(smem_base + SM_CTRL));

    if (wid == 0) {
        // =================== MMA issuer (warp 0) ===================
        int s = 0, ph = 0;
        for (int c = 0; c < NCHUNK; c++) {
            MBARRIER_WAIT_PARITY(mb_afull + 8 * s, ph);
            MBARRIER_WAIT_PARITY(mb_bfull + 8 * s, ph);
            if (elect_one_pred()) {
                TCGEN05_FENCE_AFTER();
                uint64_t ad = MAKE_SMEM_DESC(smem_base + SM_A + s * 16384);
                uint64_t bd = MAKE_SMEM_DESC(smem_base + SM_B + s * 32768);
                int nst = (c == NCHUNK - 1) ? 1 : 4;   // K=16 per MMA step
                for (int ks = 0; ks < nst; ks++) {
                    uint64_t o = (uint64_t)(ks * 2);   // +32B per 16 fp16
                    mma_f16_ss(tmem, ad + o, bd + o, MMA_IDESC, !(c == 0 && ks == 0));
                }
                TCGEN05_COMMIT(mb_mdone + 8 * s);
                if (c == NCHUNK - 1) TCGEN05_COMMIT(mb_alldone);
            }
            if (++s == NSTAGE) { s = 0; ph ^= 1; }
        }
    } else {
        // ==================== loaders (warps 1-7) ====================
        const int ltid = tid - 32;   // 0..223

        // Unit = 8 consecutive f32 (32B) -> one STS.128 of 8 fp16.
        float4 vA[2 * LPU], vB[2 * LPU];   // double buffers (chunk parity)

        auto load_unit = [&](int c, float4* v) {
            const int kvalid = KPIX - c * BK;      // 64 except last = 16
            #pragma unroll
            for (int i = 0; i < LPU; i++) {
                int u    = ltid + i * NLOAD;
                int row  = u >> 3;
                int ucol = u & 7;
                v[2 * i]     = make_float4(0.f, 0.f, 0.f, 0.f);
                v[2 * i + 1] = make_float4(0.f, 0.f, 0.f, 0.f);
                if (u < NUNIT && ucol * 8 < kvalid) {
                    const float* p = X + (long)(m0 + row) * KPIX + c * BK + ucol * 8;
                    v[2 * i]     = *(const float4*)p;
                    v[2 * i + 1] = *(const float4*)(p + 4);
                }
            }
        };

        auto store_stage = [&](int s, const float4* v) {
            char* ast = smem + SM_A + s * 16384;
            #pragma unroll
            for (int i = 0; i < LPU; i++) {
                int u    = ltid + i * NLOAD;
                int row  = u >> 3;
                int ucol = u & 7;
                if (u < NUNIT) {
                    uint32_t h01 = cvt2h(v[2*i].y,   v[2*i].x);
                    uint32_t h23 = cvt2h(v[2*i].w,   v[2*i].z);
                    uint32_t h45 = cvt2h(v[2*i+1].y, v[2*i+1].x);
                    uint32_t h67 = cvt2h(v[2*i+1].w, v[2*i+1].z);
                    uint32_t sw = sw128((uint32_t)(row * 128 + ucol * 16));
                    *(uint4*)(ast + sw) = make_uint4(h01, h23, h45, h67);
                }
            }
        };

        // per-warp fence + single-lane arrive (afull count = 7)
        auto publish = [&](int s) {
            FENCE_PROXY_ASYNC();
            __syncwarp();
            if (lid == 0) MBARRIER_ARRIVE(mb_afull + 8 * s);
        };
        auto b_copy = [&](int c, int s) {
            MBARRIER_EXPECT_TX(mb_bfull + 8 * s, 32768);
            CP_ASYNC_BULK_G2S(smem_base + SM_B + s * 32768,
                              (const void*)(g_B + c * BCHUNK_ELEMS),
                              32768, mb_bfull + 8 * s);
        };

        // prologue: B copies + A stages for chunks 0..2; chunks 3,4 in regs
        if (tid == 32) { b_copy(0, 0); b_copy(1, 1); b_copy(2, 2); }
        load_unit(0, vA);
        load_unit(1, vB);
        store_stage(0, vA);  publish(0);
        load_unit(2, vA);
        store_stage(1, vB);  publish(1);
        load_unit(3, vB);
        store_stage(2, vA);  publish(2);
        load_unit(4, vA);

        // main loop: chunk c (in buffer c&1) stored after mdone(c-3).
        int sL = 0, phL = 0;
        for (int c = NSTAGE; c < NCHUNK; c++) {
            MBARRIER_WAIT_PARITY(mb_mdone + 8 * sL, phL);
            if (tid == 32) b_copy(c, sL);
            store_stage(sL, (c & 1) ? vB : vA);
            if (c + 2 < NCHUNK) load_unit(c + 2, (c & 1) ? vB : vA);
            publish(sL);
            if (++sL == NSTAGE) { sL = 0; phL ^= 1; }
        }
    }

    // ---- all threads: wait for every MMA to complete ----
    MBARRIER_WAIT_PARITY(mb_alldone, 0);
    __syncthreads();
    TCGEN05_FENCE_AFTER();

    // ---- fused epilogue: h = relu(D + b0); out = h @ w1T + b1 ----
    const int sub  = wid & 3;          // TMEM subpartition (rows sub*32..+31)
    const int half = wid >> 2;         // 0: cols 0..127, 1: cols 128..255
    const int r    = sub * 32 + lid;
    const float* b0s = (const float*)(smem + SM_B0);
    const unsigned long long* w1p = (const unsigned long long*)(smem + SM_W1P);

    unsigned long long p2[5] = {0, 0, 0, 0, 0};
    #pragma unroll
    for (int blk = 0; blk < 4; blk++) {
        uint32_t d[32];
        TCGEN05_LD_32X32B_X32(d, tmem + half * 128 + blk * 32);
        TCGEN05_WAIT_LD();
        #pragma unroll
        for (int i = 0; i < 32; i++) {
            int j = half * 128 + blk * 32 + i;
            float h = fmaxf(__uint_as_float(d[i]) + b0s[j], 0.0f);
            unsigned long long hh = pack2(h, h);
            #pragma unroll
            for (int cc = 0; cc < 5; cc++) fma2(p2[cc], hh, w1p[j * 5 + cc]);
        }
    }
    TCGEN05_FENCE_BEFORE();

    float* outst = (float*)(smem + SM_OUT);
    if (half == 0) {
        #pragma unroll
        for (int cc = 0; cc < 5; cc++) {
            float2 f = unpack2(p2[cc]);
            outst[r * 10 + 2 * cc]     = f.x;
            outst[r * 10 + 2 * cc + 1] = f.y;
        }
    }
    __syncthreads();
    if (half == 1) {
        long m = m0 + r;
        #pragma unroll
        for (int cc = 0; cc < 5; cc++) {
            float2 f = unpack2(p2[cc]);
            out[m * NOUT + 2 * cc]     = outst[r * 10 + 2 * cc]     + f.x + b1[2 * cc];
            out[m * NOUT + 2 * cc + 1] = outst[r * 10 + 2 * cc + 1] + f.y + b1[2 * cc + 1];
        }
    }
    __syncthreads();

    if (wid == 0) {
        TCGEN05_RELINQUISH();
        TCGEN05_DEALLOC(tmem, 256);
    }

#else  // ---------------- portable fallback (non-sm_103a passes) ------------
    extern __shared__ char smem[];
    const int tid  = threadIdx.x;
    const int r    = tid & 127;
    const int half = tid >> 7;
    const int m0   = blockIdx.x * BM;
    float* hbuf = (float*)smem;

    const float* xr = X + (long)(m0 + r) * KPIX;
    for (int j = half * 100; j < half * 100 + 100; j++) {
        const float* wr = g_Weff + j * KPIX;
        float s = 0.0f;
        for (int k = 0; k < KPIX; k += 4) {
            float4 xv = *(const float4*)(xr + k);
            float4 wv = *(const float4*)(wr + k);
            s += xv.x * wv.x + xv.y * wv.y + xv.z * wv.z + xv.w * wv.w;
        }
        hbuf[r * HID + j] = fmaxf(s + b0[j], 0.0f);
    }
    __syncthreads();
    if (half == 0) {
        float o[NOUT];
        #pragma unroll
        for (int c = 0; c < NOUT; c++) o[c] = b1[c];
        for (int j = 0; j < HID; j++) {
            float h = hbuf[r * HID + j];
            #pragma unroll
            for (int c = 0; c < NOUT; c++) o[c] += h * w1[c * HID + j];
        }
        #pragma unroll
        for (int c = 0; c < NOUT; c++) out[(long)(m0 + r) * NOUT + c] = o[c];
    }
#endif
}

// ---------------------------------------------------------------------------
// kernel_launch: graph-capturable, allocation-free.
// Inputs (metadata order): x, conv_w, w0, b0, w1, b1
// ---------------------------------------------------------------------------
extern "C" void kernel_launch(void* const* d_in, const int* in_sizes, int n_in,
                              void* d_out, int out_size) {
    const float* x      = (const float*)d_in[0];
    const float* conv_w = (const float*)d_in[1];
    const float* w0     = (const float*)d_in[2];
    const float* b0     = (const float*)d_in[3];
    const float* w1     = (const float*)d_in[4];
    const float* b1     = (const float*)d_in[5];
    float* out = (float*)d_out;

    cudaFuncSetAttribute(gemm_fused_kernel,
                         cudaFuncAttributeMaxDynamicSharedMemorySize, SMEM_TOTAL);

    build_weff_kernel<<<HPAD, NCHUNK * BK>>>(conv_w, w0);
    gemm_fused_kernel<<<BATCH / BM, GEMM_THREADS, SMEM_TOTAL>>>(x, b0, w1, b1, out);
}

// round 14
// speedup vs baseline: 1.6951x; 1.0456x over previous
#include <cuda_runtime.h>
#include <cuda_fp16.h>
#include <cstdint>

// ---------------------------------------------------------------------------
// Problem constants
// ---------------------------------------------------------------------------
#define BATCH   32768
#define IMG     28
#define KPIX    784      // GEMM K
#define OUT_HW  26
#define OPIX    676
#define HID     200
#define HPAD    256      // padded hidden (GEMM N)
#define NOUT    10

#define BM      256      // M rows per CTA = 2 tiles of 128 (dual TMEM accum)
#define BK      64       // K per chunk (fp16 -> 128B rows, SW128)
#define NCHUNK  13       // 12*64 + 16
#define NSTAGE  3        // ring depth
#define GEMM_THREADS 256
#define NLOAD   224      // loader threads (warps 1..7)
#define NUNIT   2048     // 8-float units per chunk (256 rows x 8)
#define LPU     10       // units per loader thread (224*10 >= 2048)

// idesc kind::f16 (fp16 in, fp32 acc), M=128 (per tile), N=256:
//   dtype F32 (1<<4) | (N/8)<<17 | (M/16)<<24
#define MMA_IDESC 0x8400010u

#if defined(__CUDA_ARCH__) && defined(__CUDA_ARCH_FEAT_SM103_ALL)
#define HAS_TCGEN05 1
#else
#define HAS_TCGEN05 0
#endif

// elements per B chunk block: 256 x 64 fp16 = 16384 halves = 32KB
#define BCHUNK_ELEMS (HPAD * BK)

// ---------------------------------------------------------------------------
// Global scratch.
//  g_B   : per chunk, 32KB SW128 pre-swizzled fp16 Weff tile
//  g_Weff: fp32 Weff for the portable fallback path (never runs on GB300)
// ---------------------------------------------------------------------------
__device__ __align__(16) __half g_B[NCHUNK * BCHUNK_ELEMS];
__device__ __align__(16) float  g_Weff[HPAD * KPIX];

// ---------------------------------------------------------------------------
// Arch-neutral helpers
// ---------------------------------------------------------------------------
__device__ __forceinline__ uint32_t smem_to_u32(const void* p) {
    uint32_t a;
    asm("{ .reg .u64 t; cvta.to.shared.u64 t, %1; cvt.u32.u64 %0, t; }"
        : "=r"(a) : "l"(p));
    return a;
}
__device__ __forceinline__ unsigned long long pack2(float lo, float hi) {
    unsigned long long r;
    asm("mov.b64 %0, {%1, %2};" : "=l"(r) : "f"(lo), "f"(hi));
    return r;
}
__device__ __forceinline__ void fma2(unsigned long long& d,
                                     unsigned long long a,
                                     unsigned long long b) {
    asm("fma.rn.f32x2 %0, %1, %2, %0;" : "+l"(d) : "l"(a), "l"(b));
}
__device__ __forceinline__ float2 unpack2(unsigned long long v) {
    float2 f;
    asm("mov.b64 {%0, %1}, %2;" : "=f"(f.x), "=f"(f.y) : "l"(v));
    return f;
}
// packed rn convert: returns [fp16(hi_) | fp16(lo_)] (hi_ in upper 16 bits)
__device__ __forceinline__ uint32_t cvt2h(float hi_, float lo_) {
    uint32_t r;
    asm("cvt.rn.f16x2.f32 %0, %1, %2;" : "=r"(r) : "f"(hi_), "f"(lo_));
    return r;
}

// SW128 swizzle (bits [6:4] ^= bits [9:7])
__host__ __device__ __forceinline__ uint32_t sw128(uint32_t off) {
    return off ^ ((off >> 3) & 0x70);
}

#if HAS_TCGEN05
// ---------------------------------------------------------------------------
// tcgen05 / mbarrier / bulk-copy PTX helpers (sm_103a-only compilation)
// ---------------------------------------------------------------------------
__device__ __forceinline__ uint32_t elect_one_pred() {
    uint32_t pred;
    asm volatile(
        "{\n\t.reg .pred p;\n\t"
        "elect.sync _|p, 0xFFFFFFFF;\n\t"
        "selp.b32 %0, 1, 0, p;\n\t}"
        : "=r"(pred));
    return pred;
}

#define MBARRIER_INIT(addr, cnt) \
    asm volatile("mbarrier.init.shared.b64 [%0], %1;" \
        :: "r"((uint32_t)(addr)), "r"((uint32_t)(cnt)) : "memory")

#define MBARRIER_ARRIVE(addr) \
    asm volatile("mbarrier.arrive.release.cta.shared::cta.b64 _, [%0];" \
        :: "r"((uint32_t)(addr)) : "memory")

#define MBARRIER_EXPECT_TX(addr, bytes) \
    asm volatile("mbarrier.arrive.expect_tx.shared.b64 _, [%0], %1;" \
        :: "r"((uint32_t)(addr)), "r"((uint32_t)(bytes)) : "memory")

#define MBARRIER_WAIT_PARITY(addr, par) do { \
    uint32_t _m = (uint32_t)(addr); \
    uint32_t _p = (uint32_t)(par); \
    uint32_t _done; \
    asm volatile( \
        "{\n\t.reg .pred p;\n\t" \
        "mbarrier.try_wait.parity.acquire.cta.shared::cta.b64 p, [%1], %2;\n\t" \
        "selp.b32 %0, 1, 0, p;\n\t}" \
        : "=r"(_done) : "r"(_m), "r"(_p) : "memory"); \
    if (!_done) { \
        asm volatile( \
            "{\n\t.reg .pred P1;\n\t" \
            "WAIT_LOOP_%=:\n\t" \
            "mbarrier.try_wait.parity.acquire.cta.shared::cta.b64 P1, [%0], %1, 0x989680;\n\t" \
            "@P1 bra.uni WAIT_DONE_%=;\n\t" \
            "bra.uni WAIT_LOOP_%=;\n\t" \
            "WAIT_DONE_%=:\n\t}" \
            :: "r"(_m), "r"(_p) : "memory"); \
    } \
} while (0)

// plain bulk copy gmem -> smem, completion via tx mbarrier (UBLKCP)
#define CP_ASYNC_BULK_G2S(dst, src, bytes, mbar) \
    asm volatile( \
        "cp.async.bulk.shared::cluster.global.mbarrier::complete_tx::bytes " \
        "[%0], [%1], %2, [%3];" \
        :: "r"((uint32_t)(dst)), "l"(src), "r"((uint32_t)(bytes)), \
           "r"((uint32_t)(mbar)) : "memory")

#define TCGEN05_ALLOC(res_addr, ncols) \
    asm volatile("tcgen05.alloc.cta_group::1.sync.aligned.shared::cta.b32 [%0], %1;" \
        :: "r"((uint32_t)(res_addr)), "r"((uint32_t)(ncols)) : "memory")
#define TCGEN05_DEALLOC(tmem, ncols) \
    asm volatile("tcgen05.dealloc.cta_group::1.sync.aligned.b32 %0, %1;" \
        :: "r"(tmem), "r"((uint32_t)(ncols)))
#define TCGEN05_RELINQUISH() \
    asm volatile("tcgen05.relinquish_alloc_permit.cta_group::1.sync.aligned;")
#define TCGEN05_COMMIT(mbar) \
    asm volatile("tcgen05.commit.cta_group::1.mbarrier::arrive::one.shared::cluster.b64 [%0];" \
        :: "r"((uint32_t)(mbar)) : "memory")
#define TCGEN05_WAIT_LD() \
    asm volatile("tcgen05.wait::ld.sync.aligned;" ::: "memory")
#define TCGEN05_FENCE_BEFORE() \
    asm volatile("tcgen05.fence::before_thread_sync;" ::: "memory")
#define TCGEN05_FENCE_AFTER() \
    asm volatile("tcgen05.fence::after_thread_sync;" ::: "memory")
#define FENCE_PROXY_ASYNC() \
    asm volatile("fence.proxy.async.shared::cta;" ::: "memory")

#define TCGEN05_LD_32X32B_X32(r, tmem_addr) \
    asm volatile( \
        "tcgen05.ld.sync.aligned.32x32b.x32.b32 " \
        "{%0, %1, %2, %3, %4, %5, %6, %7, " \
        " %8, %9, %10, %11, %12, %13, %14, %15, " \
        " %16, %17, %18, %19, %20, %21, %22, %23, " \
        " %24, %25, %26, %27, %28, %29, %30, %31}, [%32];" \
        : "=r"((r)[0]),  "=r"((r)[1]),  "=r"((r)[2]),  "=r"((r)[3]), \
          "=r"((r)[4]),  "=r"((r)[5]),  "=r"((r)[6]),  "=r"((r)[7]), \
          "=r"((r)[8]),  "=r"((r)[9]),  "=r"((r)[10]), "=r"((r)[11]), \
          "=r"((r)[12]), "=r"((r)[13]), "=r"((r)[14]), "=r"((r)[15]), \
          "=r"((r)[16]), "=r"((r)[17]), "=r"((r)[18]), "=r"((r)[19]), \
          "=r"((r)[20]), "=r"((r)[21]), "=r"((r)[22]), "=r"((r)[23]), \
          "=r"((r)[24]), "=r"((r)[25]), "=r"((r)[26]), "=r"((r)[27]), \
          "=r"((r)[28]), "=r"((r)[29]), "=r"((r)[30]), "=r"((r)[31]) \
        : "r"(tmem_addr))

// SW128 K-major descriptor base (LBO=1, SBO=64, version=1, layout=SW128)
static constexpr uint64_t SMEM_DESC_BASE_SW128 =
    (uint64_t(2)  << 61) | (uint64_t(1) << 46) |
    (uint64_t(64) << 32) | (uint64_t(1) << 16);
#define MAKE_SMEM_DESC(addr) \
    (SMEM_DESC_BASE_SW128 | ((uint64_t)((addr) >> 4) & 0x3FFF))

__device__ __forceinline__ void mma_f16_ss(uint32_t d_tmem, uint64_t a_desc,
                                           uint64_t b_desc, uint32_t idesc,
                                           bool acc) {
    uint32_t en = acc ? 1u : 0u;
    asm volatile(
        "{\n\t.reg .pred p;\n\t"
        "setp.ne.u32 p, %5, 0;\n\t"
        "tcgen05.mma.cta_group::1.kind::f16 [%0], %1, %2, %3, "
        "{%4, %4, %4, %4}, p;\n\t}"
        :: "r"(d_tmem), "l"(a_desc), "l"(b_desc), "r"(idesc),
           "r"(0u), "r"(en)
        : "memory");
}
#endif // HAS_TCGEN05

// ---------------------------------------------------------------------------
// Kernel 1: fold conv into w0; write fp32 g_Weff (fallback) and SW128
// pre-swizzled fp16 chunk tiles g_B. grid=HPAD, block=832 (13*64).
// ---------------------------------------------------------------------------
__global__ void build_weff_kernel(const float* __restrict__ conv_w,
                                  const float* __restrict__ w0) {
    int j = blockIdx.x;      // hidden unit 0..255
    int p = threadIdx.x;     // k position 0..831
    float s = 0.0f;
    if (j < HID && p < KPIX) {
        int py = p / IMG, px = p % IMG;
        #pragma unroll
        for (int ky = 0; ky < 3; ky++)
            #pragma unroll
            for (int kx = 0; kx < 3; kx++) {
                int oy = py - ky, ox = px - kx;
                if (oy >= 0 && oy < OUT_HW && ox >= 0 && ox < OUT_HW)
                    s += conv_w[ky * 3 + kx] * w0[j * OPIX + oy * OUT_HW + ox];
            }
    }
    if (p < KPIX) g_Weff[j * KPIX + p] = s;

    int chunk = p >> 6, kin = p & 63;                // BK=64
    uint32_t off = (uint32_t)(j * 128 + kin * 2);    // bytes within 32KB tile
    uint32_t sw  = sw128(off);
    g_B[chunk * BCHUNK_ELEMS + (int)(sw >> 1)] = __float2half_rn(s);
}

// ---------------------------------------------------------------------------
// Kernel 2: fused  out = relu(X @ WeffT + b0) @ w1T + b1  (tcgen05 fp16).
// BM=256 per CTA as TWO M=128 tiles sharing each B chunk; dual TMEM
// accumulators (cols 0-255 / 256-511). grid=128 => SINGLE WAVE. 3-stage
// ring, warp-specialized, R13 low-traffic loader.
// ---------------------------------------------------------------------------
// smem byte offsets
// ctrl: tmem ptr @0; bfull[3] @16..39; afull[3] @48..71; mdone[3] @80..103;
//       alldone @112
#define SM_CTRL   0
#define SM_A      1024       // 3 stages x 32KB (t0 16KB | t1 16KB) = 98304
#define SM_B      99328      // 3 stages x 32KB = 98304
#define SM_W1P    197632     // 256*5*8 = 10240
#define SM_B0     207872     // 1024
#define SM_OUT    SM_A       // reused AFTER mainloop (A ring dead): 256*10*4
#define SMEM_TOTAL 208896    // 204KB

__global__ void __launch_bounds__(GEMM_THREADS, 1)
gemm_fused_kernel(const float* __restrict__ X,
                  const float* __restrict__ b0,
                  const float* __restrict__ w1,
                  const float* __restrict__ b1,
                  float* __restrict__ out) {
#if HAS_TCGEN05
    extern __shared__ char smem[];
    const uint32_t smem_base = smem_to_u32(smem);
    const int tid = threadIdx.x;
    const int wid = tid >> 5;
    const int lid = tid & 31;
    const int m0  = blockIdx.x * BM;

    const uint32_t mb_bfull   = smem_base + SM_CTRL + 16;  // +8*s
    const uint32_t mb_afull   = smem_base + SM_CTRL + 48;  // +8*s
    const uint32_t mb_mdone   = smem_base + SM_CTRL + 80;  // +8*s
    const uint32_t mb_alldone = smem_base + SM_CTRL + 112;

    // TMEM alloc (warp 0, collective): all 512 columns (two 256-col tiles)
    if (wid == 0) TCGEN05_ALLOC(smem_base + SM_CTRL, 512);

    // epilogue weights into smem + mbarrier init
    if (tid < HPAD) {
        int j = tid;
        float* b0s = (float*)(smem + SM_B0);
        b0s[j] = (j < HID) ? b0[j] : 0.0f;
        unsigned long long* w1p = (unsigned long long*)(smem + SM_W1P);
        #pragma unroll
        for (int cc = 0; cc < 5; cc++) {
            float a  = (j < HID) ? w1[(2 * cc) * HID + j] : 0.0f;
            float bb = (j < HID) ? w1[(2 * cc + 1) * HID + j] : 0.0f;
            w1p[j * 5 + cc] = pack2(a, bb);
        }
    }
    if (tid == 0) {
        #pragma unroll
        for (int s = 0; s < NSTAGE; s++) {
            MBARRIER_INIT(mb_bfull + 8 * s, 1);
            MBARRIER_INIT(mb_afull + 8 * s, 7);   // one arrive per loader warp
            MBARRIER_INIT(mb_mdone + 8 * s, 1);
        }
        MBARRIER_INIT(mb_alldone, 1);
    }
    __syncthreads();

    uint32_t tmem;
    asm volatile("ld.shared.b32 %0, [%1];" : "=r"(tmem) : "r"(smem_base + SM_CTRL));

    if (wid == 0) {
        // =================== MMA issuer (warp 0) ===================
        int s = 0, ph = 0;
        for (int c = 0; c < NCHUNK; c++) {
            MBARRIER_WAIT_PARITY(mb_afull + 8 * s, ph);
            MBARRIER_WAIT_PARITY(mb_bfull + 8 * s, ph);
            if (elect_one_pred()) {
                TCGEN05_FENCE_AFTER();
                uint64_t a0 = MAKE_SMEM_DESC(smem_base + SM_A + s * 32768);
                uint64_t a1 = MAKE_SMEM_DESC(smem_base + SM_A + s * 32768 + 16384);
                uint64_t bd = MAKE_SMEM_DESC(smem_base + SM_B + s * 32768);
                int nst = (c == NCHUNK - 1) ? 1 : 4;   // K=16 per MMA step
                for (int ks = 0; ks < nst; ks++) {
                    uint64_t o = (uint64_t)(ks * 2);   // +32B per 16 fp16
                    bool acc = !(c == 0 && ks == 0);
                    mma_f16_ss(tmem,       a0 + o, bd + o, MMA_IDESC, acc);
                    mma_f16_ss(tmem + 256, a1 + o, bd + o, MMA_IDESC, acc);
                }
                TCGEN05_COMMIT(mb_mdone + 8 * s);
                if (c == NCHUNK - 1) TCGEN05_COMMIT(mb_alldone);
            }
            if (++s == NSTAGE) { s = 0; ph ^= 1; }
        }
    } else {
        // ==================== loaders (warps 1-7) ====================
        const int ltid = tid - 32;   // 0..223

        // Unit = 8 consecutive f32 (32B) -> one STS.128 of 8 fp16.
        auto load_regs = [&](int c, float4* v) {
            const int kvalid = KPIX - c * BK;      // 64 except last = 16
            #pragma unroll
            for (int i = 0; i < LPU; i++) {
                int u    = ltid + i * NLOAD;
                int row  = u >> 3;
                int ucol = u & 7;
                v[2 * i]     = make_float4(0.f, 0.f, 0.f, 0.f);
                v[2 * i + 1] = make_float4(0.f, 0.f, 0.f, 0.f);
                if (u < NUNIT && ucol * 8 < kvalid) {
                    const float* p = X + (long)(m0 + row) * KPIX + c * BK + ucol * 8;
                    v[2 * i]     = *(const float4*)p;
                    v[2 * i + 1] = *(const float4*)(p + 4);
                }
            }
        };

        auto store_stage = [&](int s, const float4* v) {
            char* ast = smem + SM_A + s * 32768;
            #pragma unroll
            for (int i = 0; i < LPU; i++) {
                int u    = ltid + i * NLOAD;
                int row  = u >> 3;
                int ucol = u & 7;
                if (u < NUNIT) {
                    int tile = row >> 7;           // 0 or 1
                    int r1   = row & 127;
                    uint32_t h01 = cvt2h(v[2*i].y,   v[2*i].x);
                    uint32_t h23 = cvt2h(v[2*i].w,   v[2*i].z);
                    uint32_t h45 = cvt2h(v[2*i+1].y, v[2*i+1].x);
                    uint32_t h67 = cvt2h(v[2*i+1].w, v[2*i+1].z);
                    uint32_t sw = sw128((uint32_t)(r1 * 128 + ucol * 16));
                    *(uint4*)(ast + tile * 16384 + sw) =
                        make_uint4(h01, h23, h45, h67);
                }
            }
        };

        // per-warp fence + single-lane arrive (afull count = 7)
        auto publish = [&](int s) {
            FENCE_PROXY_ASYNC();
            __syncwarp();
            if (lid == 0) MBARRIER_ARRIVE(mb_afull + 8 * s);
        };
        auto b_copy = [&](int c, int s) {
            MBARRIER_EXPECT_TX(mb_bfull + 8 * s, 32768);
            CP_ASYNC_BULK_G2S(smem_base + SM_B + s * 32768,
                              (const void*)(g_B + c * BCHUNK_ELEMS),
                              32768, mb_bfull + 8 * s);
        };

        float4 v[2 * LPU];   // 20 float4

        // prologue: fill all 3 stages (chunks 0..2)
        if (tid == 32) { b_copy(0, 0); b_copy(1, 1); b_copy(2, 2); }
        load_regs(0, v); store_stage(0, v); publish(0);
        load_regs(1, v); store_stage(1, v); publish(1);
        load_regs(2, v); store_stage(2, v); publish(2);

        // main loop: chunk c reuses stage c%3 after MMA(c-3) completes.
        int sL = 0, phL = 0;
        for (int c = NSTAGE; c < NCHUNK; c++) {
            load_regs(c, v);                     // overlaps the mdone wait
            MBARRIER_WAIT_PARITY(mb_mdone + 8 * sL, phL);
            if (tid == 32) b_copy(c, sL);
            store_stage(sL, v);
            publish(sL);
            if (++sL == NSTAGE) { sL = 0; phL ^= 1; }
        }
    }

    // ---- all threads: wait for every MMA to complete ----
    MBARRIER_WAIT_PARITY(mb_alldone, 0);
    __syncthreads();
    TCGEN05_FENCE_AFTER();

    // ---- fused epilogue: h = relu(D + b0); out = h @ w1T + b1 (both tiles)
    const int sub  = wid & 3;          // TMEM subpartition (rows sub*32..+31)
    const int half = wid >> 2;         // 0: cols 0..127, 1: cols 128..255
    const int r    = sub * 32 + lid;
    const float* b0s = (const float*)(smem + SM_B0);
    const unsigned long long* w1p = (const unsigned long long*)(smem + SM_W1P);
    float* outst = (float*)(smem + SM_OUT);   // A ring dead; 256 rows x 10

    #pragma unroll
    for (int t = 0; t < 2; t++) {
        unsigned long long p2[5] = {0, 0, 0, 0, 0};
        #pragma unroll
        for (int blk = 0; blk < 4; blk++) {
            uint32_t d[32];
            TCGEN05_LD_32X32B_X32(d, tmem + t * 256 + half * 128 + blk * 32);
            TCGEN05_WAIT_LD();
            #pragma unroll
            for (int i = 0; i < 32; i++) {
                int j = half * 128 + blk * 32 + i;
                float h = fmaxf(__uint_as_float(d[i]) + b0s[j], 0.0f);
                unsigned long long hh = pack2(h, h);
                #pragma unroll
                for (int cc = 0; cc < 5; cc++) fma2(p2[cc], hh, w1p[j * 5 + cc]);
            }
        }
        TCGEN05_FENCE_BEFORE();

        int rg = t * 128 + r;
        if (half == 0) {
            #pragma unroll
            for (int cc = 0; cc < 5; cc++) {
                float2 f = unpack2(p2[cc]);
                outst[rg * 10 + 2 * cc]     = f.x;
                outst[rg * 10 + 2 * cc + 1] = f.y;
            }
        }
        __syncthreads();
        if (half == 1) {
            long m = m0 + rg;
            #pragma unroll
            for (int cc = 0; cc < 5; cc++) {
                float2 f = unpack2(p2[cc]);
                out[m * NOUT + 2 * cc]     = outst[rg * 10 + 2 * cc]     + f.x + b1[2 * cc];
                out[m * NOUT + 2 * cc + 1] = outst[rg * 10 + 2 * cc + 1] + f.y + b1[2 * cc + 1];
            }
        }
        __syncthreads();
    }

    if (wid == 0) {
        TCGEN05_RELINQUISH();
        TCGEN05_DEALLOC(tmem, 512);
    }

#else  // ---------------- portable fallback (non-sm_103a passes) ------------
    extern __shared__ char smem[];
    const int tid = threadIdx.x;
    const int m0  = blockIdx.x * BM;
    // Each thread handles one of 256 rows entirely.
    const float* xr = X + (long)(m0 + tid) * KPIX;
    float o[NOUT];
    #pragma unroll
    for (int c = 0; c < NOUT; c++) o[c] = b1[c];
    for (int j = 0; j < HID; j++) {
        const float* wr = g_Weff + j * KPIX;
        float s = 0.0f;
        for (int k = 0; k < KPIX; k += 4) {
            float4 xv = *(const float4*)(xr + k);
            float4 wv = *(const float4*)(wr + k);
            s += xv.x * wv.x + xv.y * wv.y + xv.z * wv.z + xv.w * wv.w;
        }
        float h = fmaxf(s + b0[j], 0.0f);
        #pragma unroll
        for (int c = 0; c < NOUT; c++) o[c] += h * w1[c * HID + j];
    }
    #pragma unroll
    for (int c = 0; c < NOUT; c++) out[(long)(m0 + tid) * NOUT + c] = o[c];
#endif
}

// ---------------------------------------------------------------------------
// kernel_launch: graph-capturable, allocation-free.
// Inputs (metadata order): x, conv_w, w0, b0, w1, b1
// ---------------------------------------------------------------------------
extern "C" void kernel_launch(void* const* d_in, const int* in_sizes, int n_in,
                              void* d_out, int out_size) {
    const float* x      = (const float*)d_in[0];
    const float* conv_w = (const float*)d_in[1];
    const float* w0     = (const float*)d_in[2];
    const float* b0     = (const float*)d_in[3];
    const float* w1     = (const float*)d_in[4];
    const float* b1     = (const float*)d_in[5];
    float* out = (float*)d_out;

    cudaFuncSetAttribute(gemm_fused_kernel,
                         cudaFuncAttributeMaxDynamicSharedMemorySize, SMEM_TOTAL);

    build_weff_kernel<<<HPAD, NCHUNK * BK>>>(conv_w, w0);
    gemm_fused_kernel<<<BATCH / BM, GEMM_THREADS, SMEM_TOTAL>>>(x, b0, w1, b1, out);
}

// round 15
// speedup vs baseline: 1.7544x; 1.0350x over previous
#include <cuda_runtime.h>
#include <cuda_fp16.h>
#include <cstdint>

// ---------------------------------------------------------------------------
// Problem constants
// ---------------------------------------------------------------------------
#define BATCH   32768
#define IMG     28
#define KPIX    784      // GEMM K
#define OUT_HW  26
#define OPIX    676
#define HID     200
#define HPAD    256      // padded hidden (GEMM N)
#define NOUT    10

#define BM      128      // M rows per CTA
#define BK      64       // K per chunk (fp16 -> 128B rows, SW128)
#define NCHUNK  13       // 12*64 + 16
#define NSTAGE  2        // ring depth (48KB/stage -> 108KB CTA -> 2 CTAs/SM)
#define GEMM_THREADS 256
#define NLOAD   224      // loader threads (warps 1..7)
#define NUNIT   1024     // 8-float units per chunk (128 rows x 8)
#define LPU     5        // units per loader thread (224*5 >= 1024)

// idesc kind::f16 (fp16 in, fp32 acc), M=128, N=256:
//   dtype F32 (1<<4) | (N/8)<<17 | (M/16)<<24
#define MMA_IDESC 0x8400010u

#if defined(__CUDA_ARCH__) && defined(__CUDA_ARCH_FEAT_SM103_ALL)
#define HAS_TCGEN05 1
#else
#define HAS_TCGEN05 0
#endif

// elements per B chunk block: 256 x 64 fp16 = 16384 halves = 32KB
#define BCHUNK_ELEMS (HPAD * BK)

// ---------------------------------------------------------------------------
// Global scratch.
//  g_B   : per chunk, 32KB SW128 pre-swizzled fp16 Weff tile
//  g_Weff: fp32 Weff for the portable fallback path (never runs on GB300)
// ---------------------------------------------------------------------------
__device__ __align__(16) __half g_B[NCHUNK * BCHUNK_ELEMS];
__device__ __align__(16) float  g_Weff[HPAD * KPIX];

// ---------------------------------------------------------------------------
// Arch-neutral helpers
// ---------------------------------------------------------------------------
__device__ __forceinline__ uint32_t smem_to_u32(const void* p) {
    uint32_t a;
    asm("{ .reg .u64 t; cvta.to.shared.u64 t, %1; cvt.u32.u64 %0, t; }"
        : "=r"(a) : "l"(p));
    return a;
}
__device__ __forceinline__ unsigned long long pack2(float lo, float hi) {
    unsigned long long r;
    asm("mov.b64 %0, {%1, %2};" : "=l"(r) : "f"(lo), "f"(hi));
    return r;
}
__device__ __forceinline__ void fma2(unsigned long long& d,
                                     unsigned long long a,
                                     unsigned long long b) {
    asm("fma.rn.f32x2 %0, %1, %2, %0;" : "+l"(d) : "l"(a), "l"(b));
}
__device__ __forceinline__ float2 unpack2(unsigned long long v) {
    float2 f;
    asm("mov.b64 {%0, %1}, %2;" : "=f"(f.x), "=f"(f.y) : "l"(v));
    return f;
}
// packed rn convert: returns [fp16(hi_) | fp16(lo_)] (hi_ in upper 16 bits)
__device__ __forceinline__ uint32_t cvt2h(float hi_, float lo_) {
    uint32_t r;
    asm("cvt.rn.f16x2.f32 %0, %1, %2;" : "=r"(r) : "f"(hi_), "f"(lo_));
    return r;
}

// SW128 swizzle (bits [6:4] ^= bits [9:7])
__host__ __device__ __forceinline__ uint32_t sw128(uint32_t off) {
    return off ^ ((off >> 3) & 0x70);
}

#if HAS_TCGEN05
// ---------------------------------------------------------------------------
// tcgen05 / mbarrier / bulk-copy PTX helpers (sm_103a-only compilation)
// ---------------------------------------------------------------------------
__device__ __forceinline__ uint32_t elect_one_pred() {
    uint32_t pred;
    asm volatile(
        "{\n\t.reg .pred p;\n\t"
        "elect.sync _|p, 0xFFFFFFFF;\n\t"
        "selp.b32 %0, 1, 0, p;\n\t}"
        : "=r"(pred));
    return pred;
}

#define MBARRIER_INIT(addr, cnt) \
    asm volatile("mbarrier.init.shared.b64 [%0], %1;" \
        :: "r"((uint32_t)(addr)), "r"((uint32_t)(cnt)) : "memory")

#define MBARRIER_ARRIVE(addr) \
    asm volatile("mbarrier.arrive.release.cta.shared::cta.b64 _, [%0];" \
        :: "r"((uint32_t)(addr)) : "memory")

#define MBARRIER_EXPECT_TX(addr, bytes) \
    asm volatile("mbarrier.arrive.expect_tx.shared.b64 _, [%0], %1;" \
        :: "r"((uint32_t)(addr)), "r"((uint32_t)(bytes)) : "memory")

#define MBARRIER_WAIT_PARITY(addr, par) do { \
    uint32_t _m = (uint32_t)(addr); \
    uint32_t _p = (uint32_t)(par); \
    uint32_t _done; \
    asm volatile( \
        "{\n\t.reg .pred p;\n\t" \
        "mbarrier.try_wait.parity.acquire.cta.shared::cta.b64 p, [%1], %2;\n\t" \
        "selp.b32 %0, 1, 0, p;\n\t}" \
        : "=r"(_done) : "r"(_m), "r"(_p) : "memory"); \
    if (!_done) { \
        asm volatile( \
            "{\n\t.reg .pred P1;\n\t" \
            "WAIT_LOOP_%=:\n\t" \
            "mbarrier.try_wait.parity.acquire.cta.shared::cta.b64 P1, [%0], %1, 0x989680;\n\t" \
            "@P1 bra.uni WAIT_DONE_%=;\n\t" \
            "bra.uni WAIT_LOOP_%=;\n\t" \
            "WAIT_DONE_%=:\n\t}" \
            :: "r"(_m), "r"(_p) : "memory"); \
    } \
} while (0)

// plain bulk copy gmem -> smem, completion via tx mbarrier (UBLKCP)
#define CP_ASYNC_BULK_G2S(dst, src, bytes, mbar) \
    asm volatile( \
        "cp.async.bulk.shared::cluster.global.mbarrier::complete_tx::bytes " \
        "[%0], [%1], %2, [%3];" \
        :: "r"((uint32_t)(dst)), "l"(src), "r"((uint32_t)(bytes)), \
           "r"((uint32_t)(mbar)) : "memory")

#define TCGEN05_ALLOC(res_addr, ncols) \
    asm volatile("tcgen05.alloc.cta_group::1.sync.aligned.shared::cta.b32 [%0], %1;" \
        :: "r"((uint32_t)(res_addr)), "r"((uint32_t)(ncols)) : "memory")
#define TCGEN05_DEALLOC(tmem, ncols) \
    asm volatile("tcgen05.dealloc.cta_group::1.sync.aligned.b32 %0, %1;" \
        :: "r"(tmem), "r"((uint32_t)(ncols)))
#define TCGEN05_RELINQUISH() \
    asm volatile("tcgen05.relinquish_alloc_permit.cta_group::1.sync.aligned;")
#define TCGEN05_COMMIT(mbar) \
    asm volatile("tcgen05.commit.cta_group::1.mbarrier::arrive::one.shared::cluster.b64 [%0];" \
        :: "r"((uint32_t)(mbar)) : "memory")
#define TCGEN05_WAIT_LD() \
    asm volatile("tcgen05.wait::ld.sync.aligned;" ::: "memory")
#define TCGEN05_FENCE_BEFORE() \
    asm volatile("tcgen05.fence::before_thread_sync;" ::: "memory")
#define TCGEN05_FENCE_AFTER() \
    asm volatile("tcgen05.fence::after_thread_sync;" ::: "memory")
#define FENCE_PROXY_ASYNC() \
    asm volatile("fence.proxy.async.shared::cta;" ::: "memory")

#define TCGEN05_LD_32X32B_X32(r, tmem_addr) \
    asm volatile( \
        "tcgen05.ld.sync.aligned.32x32b.x32.b32 " \
        "{%0, %1, %2, %3, %4, %5, %6, %7, " \
        " %8, %9, %10, %11, %12, %13, %14, %15, " \
        " %16, %17, %18, %19, %20, %21, %22, %23, " \
        " %24, %25, %26, %27, %28, %29, %30, %31}, [%32];" \
        : "=r"((r)[0]),  "=r"((r)[1]),  "=r"((r)[2]),  "=r"((r)[3]), \
          "=r"((r)[4]),  "=r"((r)[5]),  "=r"((r)[6]),  "=r"((r)[7]), \
          "=r"((r)[8]),  "=r"((r)[9]),  "=r"((r)[10]), "=r"((r)[11]), \
          "=r"((r)[12]), "=r"((r)[13]), "=r"((r)[14]), "=r"((r)[15]), \
          "=r"((r)[16]), "=r"((r)[17]), "=r"((r)[18]), "=r"((r)[19]), \
          "=r"((r)[20]), "=r"((r)[21]), "=r"((r)[22]), "=r"((r)[23]), \
          "=r"((r)[24]), "=r"((r)[25]), "=r"((r)[26]), "=r"((r)[27]), \
          "=r"((r)[28]), "=r"((r)[29]), "=r"((r)[30]), "=r"((r)[31]) \
        : "r"(tmem_addr))

// SW128 K-major descriptor base (LBO=1, SBO=64, version=1, layout=SW128)
static constexpr uint64_t SMEM_DESC_BASE_SW128 =
    (uint64_t(2)  << 61) | (uint64_t(1) << 46) |
    (uint64_t(64) << 32) | (uint64_t(1) << 16);
#define MAKE_SMEM_DESC(addr) \
    (SMEM_DESC_BASE_SW128 | ((uint64_t)((addr) >> 4) & 0x3FFF))

__device__ __forceinline__ void mma_f16_ss(uint32_t d_tmem, uint64_t a_desc,
                                           uint64_t b_desc, uint32_t idesc,
                                           bool acc) {
    uint32_t en = acc ? 1u : 0u;
    asm volatile(
        "{\n\t.reg .pred p;\n\t"
        "setp.ne.u32 p, %5, 0;\n\t"
        "tcgen05.mma.cta_group::1.kind::f16 [%0], %1, %2, %3, "
        "{%4, %4, %4, %4}, p;\n\t}"
        :: "r"(d_tmem), "l"(a_desc), "l"(b_desc), "r"(idesc),
           "r"(0u), "r"(en)
        : "memory");
}
#endif // HAS_TCGEN05

// ---------------------------------------------------------------------------
// Kernel 1: fold conv into w0; write fp32 g_Weff (fallback) and SW128
// pre-swizzled fp16 chunk tiles g_B. grid=HPAD, block=832 (13*64).
// ---------------------------------------------------------------------------
__global__ void build_weff_kernel(const float* __restrict__ conv_w,
                                  const float* __restrict__ w0) {
    int j = blockIdx.x;      // hidden unit 0..255
    int p = threadIdx.x;     // k position 0..831
    float s = 0.0f;
    if (j < HID && p < KPIX) {
        int py = p / IMG, px = p % IMG;
        #pragma unroll
        for (int ky = 0; ky < 3; ky++)
            #pragma unroll
            for (int kx = 0; kx < 3; kx++) {
                int oy = py - ky, ox = px - kx;
                if (oy >= 0 && oy < OUT_HW && ox >= 0 && ox < OUT_HW)
                    s += conv_w[ky * 3 + kx] * w0[j * OPIX + oy * OUT_HW + ox];
            }
    }
    if (p < KPIX) g_Weff[j * KPIX + p] = s;

    int chunk = p >> 6, kin = p & 63;                // BK=64
    uint32_t off = (uint32_t)(j * 128 + kin * 2);    // bytes within 32KB tile
    uint32_t sw  = sw128(off);
    g_B[chunk * BCHUNK_ELEMS + (int)(sw >> 1)] = __float2half_rn(s);
}

// ---------------------------------------------------------------------------
// Kernel 2: fused  out = relu(X @ WeffT + b0) @ w1T + b1  (tcgen05 fp16,
// single MMA per K-step). R15: TWO CTAs PER SM (108KB smem, <=128 regs,
// alloc-permit relinquished immediately after TMEM alloc so the co-resident
// CTA can allocate). Two independent pipelines per SM hide each other's
// commit/fence/LDG latencies.
// ---------------------------------------------------------------------------
// smem byte offsets
// ctrl: tmem ptr @0; bfull[2] @16,24; afull[2] @32,40; mdone[2] @48,56;
//       alldone @64
#define SM_CTRL   0
#define SM_A      1024       // 2 stages x 16KB = 32768
#define SM_B      33792      // 2 stages x 32KB = 65536
#define SM_W1P    99328      // 256*5*8 = 10240
#define SM_B0     109568     // 1024
#define SM_OUT    SM_A       // reused AFTER mainloop (A ring dead): 128*10*4
#define SMEM_TOTAL 110592    // 108KB -> 2 CTAs/SM

__global__ void __launch_bounds__(GEMM_THREADS, 2)
gemm_fused_kernel(const float* __restrict__ X,
                  const float* __restrict__ b0,
                  const float* __restrict__ w1,
                  const float* __restrict__ b1,
                  float* __restrict__ out) {
#if HAS_TCGEN05
    extern __shared__ char smem[];
    const uint32_t smem_base = smem_to_u32(smem);
    const int tid = threadIdx.x;
    const int wid = tid >> 5;
    const int lid = tid & 31;
    const int m0  = blockIdx.x * BM;

    const uint32_t mb_bfull   = smem_base + SM_CTRL + 16;  // +8*s
    const uint32_t mb_afull   = smem_base + SM_CTRL + 32;  // +8*s
    const uint32_t mb_mdone   = smem_base + SM_CTRL + 48;  // +8*s
    const uint32_t mb_alldone = smem_base + SM_CTRL + 64;

    // TMEM alloc: 256 cols, then IMMEDIATELY relinquish the alloc permit so
    // the co-resident CTA's alloc can proceed (R10's deadlock fix).
    if (wid == 0) {
        TCGEN05_ALLOC(smem_base + SM_CTRL, 256);
        TCGEN05_RELINQUISH();
    }

    // epilogue weights into smem + mbarrier init
    if (tid < HPAD) {
        int j = tid;
        float* b0s = (float*)(smem + SM_B0);
        b0s[j] = (j < HID) ? b0[j] : 0.0f;
        unsigned long long* w1p = (unsigned long long*)(smem + SM_W1P);
        #pragma unroll
        for (int cc = 0; cc < 5; cc++) {
            float a  = (j < HID) ? w1[(2 * cc) * HID + j] : 0.0f;
            float bb = (j < HID) ? w1[(2 * cc + 1) * HID + j] : 0.0f;
            w1p[j * 5 + cc] = pack2(a, bb);
        }
    }
    if (tid == 0) {
        #pragma unroll
        for (int s = 0; s < NSTAGE; s++) {
            MBARRIER_INIT(mb_bfull + 8 * s, 1);
            MBARRIER_INIT(mb_afull + 8 * s, 7);   // one arrive per loader warp
            MBARRIER_INIT(mb_mdone + 8 * s, 1);
        }
        MBARRIER_INIT(mb_alldone, 1);
    }
    __syncthreads();

    uint32_t tmem;
    asm volatile("ld.shared.b32 %0, [%1];" : "=r"(tmem) : "r"(smem_base + SM_CTRL));

    if (wid == 0) {
        // =================== MMA issuer (warp 0) ===================
        int phA0 = 0, phA1 = 0, phB0 = 0, phB1 = 0;
        for (int c = 0; c < NCHUNK; c++) {
            const int s = c & 1;
            if (s == 0) {
                MBARRIER_WAIT_PARITY(mb_afull,      phA0); phA0 ^= 1;
                MBARRIER_WAIT_PARITY(mb_bfull,      phB0); phB0 ^= 1;
            } else {
                MBARRIER_WAIT_PARITY(mb_afull + 8,  phA1); phA1 ^= 1;
                MBARRIER_WAIT_PARITY(mb_bfull + 8,  phB1); phB1 ^= 1;
            }
            if (elect_one_pred()) {
                TCGEN05_FENCE_AFTER();
                uint64_t ad = MAKE_SMEM_DESC(smem_base + SM_A + s * 16384);
                uint64_t bd = MAKE_SMEM_DESC(smem_base + SM_B + s * 32768);
                int nst = (c == NCHUNK - 1) ? 1 : 4;   // K=16 per MMA step
                for (int ks = 0; ks < nst; ks++) {
                    uint64_t o = (uint64_t)(ks * 2);   // +32B per 16 fp16
                    mma_f16_ss(tmem, ad + o, bd + o, MMA_IDESC, !(c == 0 && ks == 0));
                }
                TCGEN05_COMMIT(mb_mdone + 8 * s);
                if (c == NCHUNK - 1) TCGEN05_COMMIT(mb_alldone);
            }
        }
    } else {
        // ==================== loaders (warps 1-7) ====================
        const int ltid = tid - 32;   // 0..223

        // Unit = 8 consecutive f32 (32B) -> one STS.128 of 8 fp16.
        float4 v[2 * LPU];           // single chunk buffer (40 regs)

        auto load_regs = [&](int c) {
            const int kvalid = KPIX - c * BK;      // 64 except last = 16
            #pragma unroll
            for (int i = 0; i < LPU; i++) {
                int u    = ltid + i * NLOAD;
                int row  = u >> 3;
                int ucol = u & 7;
                v[2 * i]     = make_float4(0.f, 0.f, 0.f, 0.f);
                v[2 * i + 1] = make_float4(0.f, 0.f, 0.f, 0.f);
                if (u < NUNIT && ucol * 8 < kvalid) {
                    const float* p = X + (long)(m0 + row) * KPIX + c * BK + ucol * 8;
                    v[2 * i]     = *(const float4*)p;
                    v[2 * i + 1] = *(const float4*)(p + 4);
                }
            }
        };

        auto store_stage = [&](int s) {
            char* ast = smem + SM_A + s * 16384;
            #pragma unroll
            for (int i = 0; i < LPU; i++) {
                int u    = ltid + i * NLOAD;
                int row  = u >> 3;
                int ucol = u & 7;
                if (u < NUNIT) {
                    uint32_t h01 = cvt2h(v[2*i].y,   v[2*i].x);
                    uint32_t h23 = cvt2h(v[2*i].w,   v[2*i].z);
                    uint32_t h45 = cvt2h(v[2*i+1].y, v[2*i+1].x);
                    uint32_t h67 = cvt2h(v[2*i+1].w, v[2*i+1].z);
                    uint32_t sw = sw128((uint32_t)(row * 128 + ucol * 16));
                    *(uint4*)(ast + sw) = make_uint4(h01, h23, h45, h67);
                }
            }
        };

        // per-warp fence + single-lane arrive (afull count = 7)
        auto publish = [&](int s) {
            FENCE_PROXY_ASYNC();
            __syncwarp();
            if (lid == 0) MBARRIER_ARRIVE(mb_afull + 8 * s);
        };
        auto b_copy = [&](int c, int s) {
            MBARRIER_EXPECT_TX(mb_bfull + 8 * s, 32768);
            CP_ASYNC_BULK_G2S(smem_base + SM_B + s * 32768,
                              (const void*)(g_B + c * BCHUNK_ELEMS),
                              32768, mb_bfull + 8 * s);
        };

        // prologue: fill both stages (chunks 0, 1)
        if (tid == 32) { b_copy(0, 0); b_copy(1, 1); }
        load_regs(0); store_stage(0); publish(0);
        load_regs(1); store_stage(1); publish(1);

        // main loop: chunk c reuses stage c&1 after MMA(c-2) completes.
        int phM0 = 0, phM1 = 0;
        for (int c = NSTAGE; c < NCHUNK; c++) {
            const int s = c & 1;
            load_regs(c);                        // overlaps the mdone wait
            if (s == 0) { MBARRIER_WAIT_PARITY(mb_mdone,     phM0); phM0 ^= 1; }
            else        { MBARRIER_WAIT_PARITY(mb_mdone + 8, phM1); phM1 ^= 1; }
            if (tid == 32) b_copy(c, s);
            store_stage(s);
            publish(s);
        }
    }

    // ---- all threads: wait for every MMA to complete ----
    MBARRIER_WAIT_PARITY(mb_alldone, 0);
    __syncthreads();
    TCGEN05_FENCE_AFTER();

    // ---- fused epilogue: h = relu(D + b0); out = h @ w1T + b1 ----
    const int sub  = wid & 3;          // TMEM subpartition (rows sub*32..+31)
    const int half = wid >> 2;         // 0: cols 0..127, 1: cols 128..255
    const int r    = sub * 32 + lid;
    const float* b0s = (const float*)(smem + SM_B0);
    const unsigned long long* w1p = (const unsigned long long*)(smem + SM_W1P);

    unsigned long long p2[5] = {0, 0, 0, 0, 0};
    #pragma unroll
    for (int blk = 0; blk < 4; blk++) {
        uint32_t d[32];
        TCGEN05_LD_32X32B_X32(d, tmem + half * 128 + blk * 32);
        TCGEN05_WAIT_LD();
        #pragma unroll
        for (int i = 0; i < 32; i++) {
            int j = half * 128 + blk * 32 + i;
            float h = fmaxf(__uint_as_float(d[i]) + b0s[j], 0.0f);
            unsigned long long hh = pack2(h, h);
            #pragma unroll
            for (int cc = 0; cc < 5; cc++) fma2(p2[cc], hh, w1p[j * 5 + cc]);
        }
    }
    TCGEN05_FENCE_BEFORE();

    // A ring is dead after the mainloop; reuse it as output staging.
    float* outst = (float*)(smem + SM_OUT);
    if (half == 0) {
        #pragma unroll
        for (int cc = 0; cc < 5; cc++) {
            float2 f = unpack2(p2[cc]);
            outst[r * 10 + 2 * cc]     = f.x;
            outst[r * 10 + 2 * cc + 1] = f.y;
        }
    }
    __syncthreads();
    if (half == 1) {
        long m = m0 + r;
        #pragma unroll
        for (int cc = 0; cc < 5; cc++) {
            float2 f = unpack2(p2[cc]);
            out[m * NOUT + 2 * cc]     = outst[r * 10 + 2 * cc]     + f.x + b1[2 * cc];
            out[m * NOUT + 2 * cc + 1] = outst[r * 10 + 2 * cc + 1] + f.y + b1[2 * cc + 1];
        }
    }
    __syncthreads();

    if (wid == 0) {
        TCGEN05_DEALLOC(tmem, 256);
    }

#else  // ---------------- portable fallback (non-sm_103a passes) ------------
    extern __shared__ char smem[];
    const int tid  = threadIdx.x;
    const int r    = tid & 127;
    const int half = tid >> 7;
    const int m0   = blockIdx.x * BM;
    float* hbuf = (float*)smem;   // 128*200*4 = 100KB <= 108KB ✓

    const float* xr = X + (long)(m0 + r) * KPIX;
    for (int j = half * 100; j < half * 100 + 100; j++) {
        const float* wr = g_Weff + j * KPIX;
        float s = 0.0f;
        for (int k = 0; k < KPIX; k += 4) {
            float4 xv = *(const float4*)(xr + k);
            float4 wv = *(const float4*)(wr + k);
            s += xv.x * wv.x + xv.y * wv.y + xv.z * wv.z + xv.w * wv.w;
        }
        hbuf[r * HID + j] = fmaxf(s + b0[j], 0.0f);
    }
    __syncthreads();
    if (half == 0) {
        float o[NOUT];
        #pragma unroll
        for (int c = 0; c < NOUT; c++) o[c] = b1[c];
        for (int j = 0; j < HID; j++) {
            float h = hbuf[r * HID + j];
            #pragma unroll
            for (int c = 0; c < NOUT; c++) o[c] += h * w1[c * HID + j];
        }
        #pragma unroll
        for (int c = 0; c < NOUT; c++) out[(long)(m0 + r) * NOUT + c] = o[c];
    }
#endif
}

// ---------------------------------------------------------------------------
// kernel_launch: graph-capturable, allocation-free.
// Inputs (metadata order): x, conv_w, w0, b0, w1, b1
// ---------------------------------------------------------------------------
extern "C" void kernel_launch(void* const* d_in, const int* in_sizes, int n_in,
                              void* d_out, int out_size) {
    const float* x      = (const float*)d_in[0];
    const float* conv_w = (const float*)d_in[1];
    const float* w0     = (const float*)d_in[2];
    const float* b0     = (const float*)d_in[3];
    const float* w1     = (const float*)d_in[4];
    const float* b1     = (const float*)d_in[5];
    float* out = (float*)d_out;

    cudaFuncSetAttribute(gemm_fused_kernel,
                         cudaFuncAttributeMaxDynamicSharedMemorySize, SMEM_TOTAL);

    build_weff_kernel<<<HPAD, NCHUNK * BK>>>(conv_w, w0);
    gemm_fused_kernel<<<BATCH / BM, GEMM_THREADS, SMEM_TOTAL>>>(x, b0, w1, b1, out);
}